// round 7
// baseline (speedup 1.0000x reference)
#include <cuda_runtime.h>
#include <cuda_bf16.h>
#include <math.h>
#include <stdint.h>

// Problem constants
#define BB   2
#define SS   2048
#define HH   16
#define DD   64
#define HID  1024
#define MM   (BB*SS)        // 4096
#define BH   (BB*HH)        // 32

// Scratch (device globals; allocation-guard safe)
__device__ float g_q[BH * SS * DD];   // [bh][s][d]
__device__ float g_k[BH * SS * DD];
__device__ float g_v[BH * SS * DD];
__device__ float g_ctx[MM * HID];     // [b*S+s][h*64+d]

// omega[l] = 10000^(-l/10)
__device__ __constant__ float OMEGA[10] = {
    1.0f, 0.3981071705534972f, 0.15848931924611134f, 0.0630957344480193f,
    0.025118864315095794f, 0.01f, 0.003981071705534973f, 0.001584893192461114f,
    0.000630957344480193f, 0.00025118864315095795f
};

// ----------------------------------------------------------------------------
// TF32 helpers
// ----------------------------------------------------------------------------
__device__ __forceinline__ uint32_t f2tf32(float x) {
    uint32_t r;
    asm("cvt.rna.tf32.f32 %0, %1;" : "=r"(r) : "f"(x));
    return r;
}

__device__ __forceinline__ void mma_tf32(float* d, uint32_t a0, uint32_t a1,
                                         uint32_t a2, uint32_t a3,
                                         uint32_t b0, uint32_t b1) {
    asm volatile(
        "mma.sync.aligned.m16n8k8.row.col.f32.tf32.tf32.f32 "
        "{%0,%1,%2,%3}, {%4,%5,%6,%7}, {%8,%9}, {%0,%1,%2,%3};"
        : "+f"(d[0]), "+f"(d[1]), "+f"(d[2]), "+f"(d[3])
        : "r"(a0), "r"(a1), "r"(a2), "r"(a3), "r"(b0), "r"(b1));
}

__device__ __forceinline__ uint4 lds128(const uint32_t* p) {
    return *(const uint4*)p;
}

// ============================================================================
// GEMM kernels: k-grouped smem layout (BK=16).
// Row of 16 k-values stored at p = 4*(k&3) + (k>>2); thread t reads one v4 at
// word offset 4t -> k = {t, t+4, t+8, t+12} = both k-steps' fragment values.
// A: [m][k-grouped] stride 20.  B: transposed [n][k-grouped] stride 20.
// ============================================================================
#define GST 20

// ----------------------------------------------------------------------------
// QKV projection: C = X @ W + b -> [bh][s][d], RoPE fused for q,k.
// BM=128, BN=128, BK=16. Warp grid 4x2, warp tile 32x64. grid (8,32,3).
// ----------------------------------------------------------------------------
__global__ __launch_bounds__(256) void qkv_mma_kernel(
    const float* __restrict__ X,
    const float* __restrict__ Wq, const float* __restrict__ bq,
    const float* __restrict__ Wk, const float* __restrict__ bk,
    const float* __restrict__ Wv, const float* __restrict__ bv)
{
    const int z = blockIdx.z;
    const float* __restrict__ W    = (z == 0) ? Wq : (z == 1) ? Wk : Wv;
    const float* __restrict__ bias = (z == 0) ? bq : (z == 1) ? bk : bv;
    float* __restrict__ dst        = (z == 0) ? g_q : (z == 1) ? g_k : g_v;

    __shared__ uint32_t As[2][128][GST];
    __shared__ uint32_t Bt[2][128][GST];   // [n][k-grouped]

    const int m0 = blockIdx.y * 128;
    const int n0 = blockIdx.x * 128;
    const int tid = threadIdx.x;
    const int wid = tid >> 5, lane = tid & 31;
    const int g = lane >> 2, t = lane & 3;
    const int wm = wid >> 1, wn = wid & 1;

    // A staging: thread covers rows arow, arow+64; gmem k-cols ac4..ac4+3
    const int arow = tid >> 2, aq = tid & 3, ac4 = aq * 4;
    // B staging: thread covers n-col bn, k-half bkh (8 k values)
    const int bn = tid & 127, bkh = tid >> 7;

    float acc[2][8][4];
#pragma unroll
    for (int i = 0; i < 2; i++)
#pragma unroll
        for (int j = 0; j < 8; j++)
#pragma unroll
            for (int r = 0; r < 4; r++) acc[i][j][r] = 0.0f;

    float4 ra[2];
    float rbv[8];

    // preload k0 = 0
#pragma unroll
    for (int u = 0; u < 2; u++)
        ra[u] = *(const float4*)(X + (size_t)(m0 + arow + u * 64) * HID + ac4);
#pragma unroll
    for (int kk = 0; kk < 8; kk++)
        rbv[kk] = W[(size_t)(8 * bkh + kk) * HID + n0 + bn];
#pragma unroll
    for (int u = 0; u < 2; u++) {
        uint32_t* pa = &As[0][arow + u * 64][aq];   // p = 4j + aq
        pa[0] = f2tf32(ra[u].x); pa[4] = f2tf32(ra[u].y);
        pa[8] = f2tf32(ra[u].z); pa[12] = f2tf32(ra[u].w);
    }
#pragma unroll
    for (int kk = 0; kk < 8; kk++) {
        int p = ((kk & 3) << 2) + (bkh << 1) + (kk >> 2);
        Bt[0][bn][p] = f2tf32(rbv[kk]);
    }
    __syncthreads();

    int buf = 0;
    for (int k0 = 0; k0 < HID; k0 += 16) {
        const bool has_next = (k0 + 16 < HID);
        if (has_next) {
#pragma unroll
            for (int u = 0; u < 2; u++)
                ra[u] = *(const float4*)(X + (size_t)(m0 + arow + u * 64) * HID + k0 + 16 + ac4);
#pragma unroll
            for (int kk = 0; kk < 8; kk++)
                rbv[kk] = W[(size_t)(k0 + 16 + 8 * bkh + kk) * HID + n0 + bn];
        }

        // A fragments: one v4 per (ma, row-half)
        uint4 va0 = lds128(&As[buf][wm * 32 + g][4 * t]);
        uint4 vb0 = lds128(&As[buf][wm * 32 + g + 8][4 * t]);
        uint4 va1 = lds128(&As[buf][wm * 32 + 16 + g][4 * t]);
        uint4 vb1 = lds128(&As[buf][wm * 32 + 24 + g][4 * t]);

#pragma unroll
        for (int nf = 0; nf < 8; nf++) {
            uint4 w = lds128(&Bt[buf][wn * 64 + nf * 8 + g][4 * t]);
            mma_tf32(acc[0][nf], va0.x, vb0.x, va0.y, vb0.y, w.x, w.y);
            mma_tf32(acc[1][nf], va1.x, vb1.x, va1.y, vb1.y, w.x, w.y);
            mma_tf32(acc[0][nf], va0.z, vb0.z, va0.w, vb0.w, w.z, w.w);
            mma_tf32(acc[1][nf], va1.z, vb1.z, va1.w, vb1.w, w.z, w.w);
        }

        if (has_next) {
            const int nb = buf ^ 1;
#pragma unroll
            for (int u = 0; u < 2; u++) {
                uint32_t* pa = &As[nb][arow + u * 64][aq];
                pa[0] = f2tf32(ra[u].x); pa[4] = f2tf32(ra[u].y);
                pa[8] = f2tf32(ra[u].z); pa[12] = f2tf32(ra[u].w);
            }
#pragma unroll
            for (int kk = 0; kk < 8; kk++) {
                int p = ((kk & 3) << 2) + (bkh << 1) + (kk >> 2);
                Bt[nb][bn][p] = f2tf32(rbv[kk]);
            }
        }
        __syncthreads();
        buf ^= 1;
    }

    // Epilogue: +bias, fused axial RoPE (q,k), scatter to [bh][s][d]
    const bool do_rope = (z < 2);
#pragma unroll
    for (int ma = 0; ma < 2; ma++) {
#pragma unroll
        for (int na = 0; na < 8; na++) {
            int m = m0 + wm * 32 + ma * 16 + g;
            int n = n0 + wn * 64 + na * 8 + 2 * t;
            float b0 = bias[n], b1 = bias[n + 1];
            int h = n >> 6, d = n & 63;

            float y00 = acc[ma][na][0] + b0;
            float y01 = acc[ma][na][1] + b1;
            float y10 = acc[ma][na][2] + b0;
            float y11 = acc[ma][na][3] + b1;

            if (do_rope && d < 60) {
                int seg = d / 20;
                int j = d - seg * 20;
                int l0 = (j < 10) ? j : j - 10;
                int l1 = (j + 1 < 10) ? j + 1 : j - 9;
                float om0 = OMEGA[l0], om1 = OMEGA[l1];
                {
                    int s = m & 2047;
                    int pos = (seg == 0) ? (s >> 8) : (seg == 1) ? ((s >> 4) & 15) : (s & 15);
                    float p = (float)pos;
                    float sn0, cs0, sn1, cs1;
                    sincosf(p * om0, &sn0, &cs0);
                    sincosf(p * om1, &sn1, &cs1);
                    float r0 = y00 * cs0 - y01 * sn0;
                    float r1 = y01 * cs1 + y00 * sn1;
                    y00 = r0; y01 = r1;
                }
                {
                    int s = (m + 8) & 2047;
                    int pos = (seg == 0) ? (s >> 8) : (seg == 1) ? ((s >> 4) & 15) : (s & 15);
                    float p = (float)pos;
                    float sn0, cs0, sn1, cs1;
                    sincosf(p * om0, &sn0, &cs0);
                    sincosf(p * om1, &sn1, &cs1);
                    float r0 = y10 * cs0 - y11 * sn0;
                    float r1 = y11 * cs1 + y10 * sn1;
                    y10 = r0; y11 = r1;
                }
            }
            {
                int b = m >> 11, s = m & 2047;
                float2 v = { y00, y01 };
                *(float2*)(dst + (((size_t)((b << 4) + h)) * SS + s) * DD + d) = v;
            }
            {
                int m2 = m + 8;
                int b = m2 >> 11, s = m2 & 2047;
                float2 v = { y10, y11 };
                *(float2*)(dst + (((size_t)((b << 4) + h)) * SS + s) * DD + d) = v;
            }
        }
    }
}

// ============================================================================
// Flash attention, k-grouped layouts (64-wide rows).
// p(k) = 16*(k>>4) + 4*(k&3) + ((k>>2)&3). Thread t, chunk m reads v4 at word
// 16m+4t -> k = {16m+t, 16m+t+4, 16m+t+8, 16m+t+12} = k-steps kb=2m, 2m+1.
// Q/P: [row][d-grouped]; K: [key][d-grouped]; V transposed: [d][key-grouped].
// Row stride 76 words. grid (16, 32), 256 thr, ~152 KB smem.
// ============================================================================
#define FST 76
#define SM_Q 0
#define SM_K (SM_Q + 128 * FST)
#define SM_V (SM_K + 2 * 64 * FST)
#define SM_P (SM_V + 2 * 64 * FST)
#define FLASH_SMEM_WORDS (SM_P + 128 * FST)
#define FLASH_SMEM_BYTES (FLASH_SMEM_WORDS * 4)

__global__ __launch_bounds__(256) void flash_kernel()
{
    extern __shared__ uint32_t sm[];
    uint32_t* __restrict__ Qs = sm + SM_Q;
    uint32_t* __restrict__ Ps = sm + SM_P;

    const int bh = blockIdx.y;
    const int q0 = blockIdx.x * 128;
    const float* __restrict__ Q = g_q + (size_t)bh * SS * DD;
    const float* __restrict__ K = g_k + (size_t)bh * SS * DD;
    const float* __restrict__ V = g_v + (size_t)bh * SS * DD;

    const int tid = threadIdx.x;
    const int wid = tid >> 5, lane = tid & 31;
    const int g = lane >> 2, t = lane & 3;
    const int mr = wid * 16;

    // K staging: rows krow+16u, d-cols 4*kq..+3
    const int krow = tid >> 4, kq = tid & 15;
    // V staging (transposed): d-col vd, key-quarter q4 (16 keys)
    const int vd = tid & 63, q4 = tid >> 6;

    // Load Q tile (128x64) pre-scaled by 0.125, grouped layout
#pragma unroll
    for (int i = tid; i < 128 * 16; i += 256) {
        int row = i >> 4, qq = i & 15;
        float4 v = *(const float4*)(Q + (size_t)(q0 + row) * DD + qq * 4);
        uint32_t* p = Qs + row * FST + 16 * (qq >> 2) + (qq & 3);  // +4j
        p[0] = f2tf32(0.125f * v.x); p[4]  = f2tf32(0.125f * v.y);
        p[8] = f2tf32(0.125f * v.z); p[12] = f2tf32(0.125f * v.w);
    }

    float4 rk[4];
    float rvv[16];
    // preload tile 0
#pragma unroll
    for (int u = 0; u < 4; u++)
        rk[u] = *(const float4*)(K + (size_t)(krow + u * 16) * DD + kq * 4);
#pragma unroll
    for (int kk = 0; kk < 16; kk++)
        rvv[kk] = V[(size_t)(16 * q4 + kk) * DD + vd];
#pragma unroll
    for (int u = 0; u < 4; u++) {
        uint32_t* p = sm + SM_K + (krow + u * 16) * FST + 16 * (kq >> 2) + (kq & 3);
        p[0] = f2tf32(rk[u].x); p[4]  = f2tf32(rk[u].y);
        p[8] = f2tf32(rk[u].z); p[12] = f2tf32(rk[u].w);
    }
#pragma unroll
    for (int kk = 0; kk < 16; kk++) {
        int p = 16 * q4 + 4 * (kk & 3) + (kk >> 2);
        sm[SM_V + vd * FST + p] = f2tf32(rvv[kk]);
    }
    __syncthreads();

    float accO[8][4];
#pragma unroll
    for (int j = 0; j < 8; j++)
#pragma unroll
        for (int r = 0; r < 4; r++) accO[j][r] = 0.0f;
    float m0 = -1e30f, m1 = -1e30f, l0 = 0.0f, l1 = 0.0f;

    int buf = 0;
    for (int kt = 0; kt < SS; kt += 64) {
        const bool has_next = (kt + 64 < SS);
        if (has_next) {
#pragma unroll
            for (int u = 0; u < 4; u++)
                rk[u] = *(const float4*)(K + (size_t)(kt + 64 + krow + u * 16) * DD + kq * 4);
#pragma unroll
            for (int kk = 0; kk < 16; kk++)
                rvv[kk] = V[(size_t)(kt + 64 + 16 * q4 + kk) * DD + vd];
        }
        const uint32_t* __restrict__ Ksb = sm + SM_K + buf * 64 * FST;
        const uint32_t* __restrict__ Vsb = sm + SM_V + buf * 64 * FST;

        // S = (0.125 Q) K^T
        float accS[8][4];
#pragma unroll
        for (int j = 0; j < 8; j++)
#pragma unroll
            for (int r = 0; r < 4; r++) accS[j][r] = 0.0f;

#pragma unroll
        for (int m = 0; m < 4; m++) {
            uint4 qa = lds128(Qs + (mr + g) * FST + 16 * m + 4 * t);
            uint4 qb = lds128(Qs + (mr + g + 8) * FST + 16 * m + 4 * t);
#pragma unroll
            for (int nf = 0; nf < 8; nf++) {
                uint4 kw = lds128(Ksb + (nf * 8 + g) * FST + 16 * m + 4 * t);
                mma_tf32(accS[nf], qa.x, qb.x, qa.y, qb.y, kw.x, kw.y);
                mma_tf32(accS[nf], qa.z, qb.z, qa.w, qb.w, kw.z, kw.w);
            }
        }

        // Online softmax
        float r0 = -1e30f, r1 = -1e30f;
#pragma unroll
        for (int nf = 0; nf < 8; nf++) {
            r0 = fmaxf(r0, fmaxf(accS[nf][0], accS[nf][1]));
            r1 = fmaxf(r1, fmaxf(accS[nf][2], accS[nf][3]));
        }
        r0 = fmaxf(r0, __shfl_xor_sync(0xffffffffu, r0, 1));
        r0 = fmaxf(r0, __shfl_xor_sync(0xffffffffu, r0, 2));
        r1 = fmaxf(r1, __shfl_xor_sync(0xffffffffu, r1, 1));
        r1 = fmaxf(r1, __shfl_xor_sync(0xffffffffu, r1, 2));

        float mn0 = fmaxf(m0, r0);
        float mn1 = fmaxf(m1, r1);
        float al0 = __expf(m0 - mn0);
        float al1 = __expf(m1 - mn1);
        m0 = mn0; m1 = mn1;

        float s0 = 0.0f, s1 = 0.0f;
#pragma unroll
        for (int nf = 0; nf < 8; nf++) {
            float p00 = __expf(accS[nf][0] - m0);
            float p01 = __expf(accS[nf][1] - m0);
            float p10 = __expf(accS[nf][2] - m1);
            float p11 = __expf(accS[nf][3] - m1);
            s0 += p00 + p01;
            s1 += p10 + p11;
            int c = nf * 8 + 2 * t;                       // even
            int pp = 16 * (c >> 4) + 4 * (c & 3) + ((c >> 2) & 3);
            Ps[(mr + g) * FST + pp]         = f2tf32(p00);
            Ps[(mr + g) * FST + pp + 4]     = f2tf32(p01);   // c+1 -> p+4
            Ps[(mr + g + 8) * FST + pp]     = f2tf32(p10);
            Ps[(mr + g + 8) * FST + pp + 4] = f2tf32(p11);
        }
        s0 += __shfl_xor_sync(0xffffffffu, s0, 1);
        s0 += __shfl_xor_sync(0xffffffffu, s0, 2);
        s1 += __shfl_xor_sync(0xffffffffu, s1, 1);
        s1 += __shfl_xor_sync(0xffffffffu, s1, 2);
        l0 = l0 * al0 + s0;
        l1 = l1 * al1 + s1;

#pragma unroll
        for (int nf = 0; nf < 8; nf++) {
            accO[nf][0] *= al0;
            accO[nf][1] *= al0;
            accO[nf][2] *= al1;
            accO[nf][3] *= al1;
        }
        __syncwarp();   // P rows are warp-private

        // O += P @ V  (contraction over 64 keys; Vsb is [d][key-grouped])
#pragma unroll
        for (int m = 0; m < 4; m++) {
            uint4 pa = lds128(Ps + (mr + g) * FST + 16 * m + 4 * t);
            uint4 pb = lds128(Ps + (mr + g + 8) * FST + 16 * m + 4 * t);
#pragma unroll
            for (int nf = 0; nf < 8; nf++) {
                uint4 vw = lds128(Vsb + (nf * 8 + g) * FST + 16 * m + 4 * t);
                mma_tf32(accO[nf], pa.x, pb.x, pa.y, pb.y, vw.x, vw.y);
                mma_tf32(accO[nf], pa.z, pb.z, pa.w, pb.w, vw.z, vw.w);
            }
        }

        if (has_next) {
            const int nb = buf ^ 1;
#pragma unroll
            for (int u = 0; u < 4; u++) {
                uint32_t* p = sm + SM_K + (nb * 64 + krow + u * 16) * FST + 16 * (kq >> 2) + (kq & 3);
                p[0] = f2tf32(rk[u].x); p[4]  = f2tf32(rk[u].y);
                p[8] = f2tf32(rk[u].z); p[12] = f2tf32(rk[u].w);
            }
#pragma unroll
            for (int kk = 0; kk < 16; kk++) {
                int p = 16 * q4 + 4 * (kk & 3) + (kk >> 2);
                sm[SM_V + (nb * 64 + vd) * FST + p] = f2tf32(rvv[kk]);
            }
        }
        __syncthreads();
        buf ^= 1;
    }

    // Epilogue: normalize, write flat ctx layout
    const float inv0 = 1.0f / l0;
    const float inv1 = 1.0f / l1;
    const int bb = bh >> 4, h = bh & 15;
    const int s0r = q0 + mr + g;
#pragma unroll
    for (int nf = 0; nf < 8; nf++) {
        int d = nf * 8 + 2 * t;
        float2 v0 = { accO[nf][0] * inv0, accO[nf][1] * inv0 };
        float2 v1 = { accO[nf][2] * inv1, accO[nf][3] * inv1 };
        *(float2*)(g_ctx + ((size_t)(bb * SS + s0r)) * HID + h * DD + d) = v0;
        *(float2*)(g_ctx + ((size_t)(bb * SS + s0r + 8)) * HID + h * DD + d) = v1;
    }
}

// ----------------------------------------------------------------------------
// Output projection: out = ctx @ Wo + bo. Same structure as qkv.
// ----------------------------------------------------------------------------
__global__ __launch_bounds__(256) void oproj_mma_kernel(
    const float* __restrict__ Wo, const float* __restrict__ bo,
    float* __restrict__ out)
{
    __shared__ uint32_t As[2][128][GST];
    __shared__ uint32_t Bt[2][128][GST];

    const int m0 = blockIdx.y * 128;
    const int n0 = blockIdx.x * 128;
    const int tid = threadIdx.x;
    const int wid = tid >> 5, lane = tid & 31;
    const int g = lane >> 2, t = lane & 3;
    const int wm = wid >> 1, wn = wid & 1;

    const int arow = tid >> 2, aq = tid & 3, ac4 = aq * 4;
    const int bn = tid & 127, bkh = tid >> 7;

    float acc[2][8][4];
#pragma unroll
    for (int i = 0; i < 2; i++)
#pragma unroll
        for (int j = 0; j < 8; j++)
#pragma unroll
            for (int r = 0; r < 4; r++) acc[i][j][r] = 0.0f;

    float4 ra[2];
    float rbv[8];

#pragma unroll
    for (int u = 0; u < 2; u++)
        ra[u] = *(const float4*)(g_ctx + (size_t)(m0 + arow + u * 64) * HID + ac4);
#pragma unroll
    for (int kk = 0; kk < 8; kk++)
        rbv[kk] = Wo[(size_t)(8 * bkh + kk) * HID + n0 + bn];
#pragma unroll
    for (int u = 0; u < 2; u++) {
        uint32_t* pa = &As[0][arow + u * 64][aq];
        pa[0] = f2tf32(ra[u].x); pa[4] = f2tf32(ra[u].y);
        pa[8] = f2tf32(ra[u].z); pa[12] = f2tf32(ra[u].w);
    }
#pragma unroll
    for (int kk = 0; kk < 8; kk++) {
        int p = ((kk & 3) << 2) + (bkh << 1) + (kk >> 2);
        Bt[0][bn][p] = f2tf32(rbv[kk]);
    }
    __syncthreads();

    int buf = 0;
    for (int k0 = 0; k0 < HID; k0 += 16) {
        const bool has_next = (k0 + 16 < HID);
        if (has_next) {
#pragma unroll
            for (int u = 0; u < 2; u++)
                ra[u] = *(const float4*)(g_ctx + (size_t)(m0 + arow + u * 64) * HID + k0 + 16 + ac4);
#pragma unroll
            for (int kk = 0; kk < 8; kk++)
                rbv[kk] = Wo[(size_t)(k0 + 16 + 8 * bkh + kk) * HID + n0 + bn];
        }

        uint4 va0 = lds128(&As[buf][wm * 32 + g][4 * t]);
        uint4 vb0 = lds128(&As[buf][wm * 32 + g + 8][4 * t]);
        uint4 va1 = lds128(&As[buf][wm * 32 + 16 + g][4 * t]);
        uint4 vb1 = lds128(&As[buf][wm * 32 + 24 + g][4 * t]);

#pragma unroll
        for (int nf = 0; nf < 8; nf++) {
            uint4 w = lds128(&Bt[buf][wn * 64 + nf * 8 + g][4 * t]);
            mma_tf32(acc[0][nf], va0.x, vb0.x, va0.y, vb0.y, w.x, w.y);
            mma_tf32(acc[1][nf], va1.x, vb1.x, va1.y, vb1.y, w.x, w.y);
            mma_tf32(acc[0][nf], va0.z, vb0.z, va0.w, vb0.w, w.z, w.w);
            mma_tf32(acc[1][nf], va1.z, vb1.z, va1.w, vb1.w, w.z, w.w);
        }

        if (has_next) {
            const int nb = buf ^ 1;
#pragma unroll
            for (int u = 0; u < 2; u++) {
                uint32_t* pa = &As[nb][arow + u * 64][aq];
                pa[0] = f2tf32(ra[u].x); pa[4] = f2tf32(ra[u].y);
                pa[8] = f2tf32(ra[u].z); pa[12] = f2tf32(ra[u].w);
            }
#pragma unroll
            for (int kk = 0; kk < 8; kk++) {
                int p = ((kk & 3) << 2) + (bkh << 1) + (kk >> 2);
                Bt[nb][bn][p] = f2tf32(rbv[kk]);
            }
        }
        __syncthreads();
        buf ^= 1;
    }

#pragma unroll
    for (int ma = 0; ma < 2; ma++) {
#pragma unroll
        for (int na = 0; na < 8; na++) {
            int m = m0 + wm * 32 + ma * 16 + g;
            int n = n0 + wn * 64 + na * 8 + 2 * t;
            float b0 = bo[n], b1 = bo[n + 1];
            float2 v0 = { acc[ma][na][0] + b0, acc[ma][na][1] + b1 };
            float2 v1 = { acc[ma][na][2] + b0, acc[ma][na][3] + b1 };
            *(float2*)(out + (size_t)m * HID + n) = v0;
            *(float2*)(out + (size_t)(m + 8) * HID + n) = v1;
        }
    }
}

// ----------------------------------------------------------------------------
extern "C" void kernel_launch(void* const* d_in, const int* in_sizes, int n_in,
                              void* d_out, int out_size)
{
    const float* X  = (const float*)d_in[0];
    const float* Wq = (const float*)d_in[1];
    const float* bq = (const float*)d_in[2];
    const float* Wk = (const float*)d_in[3];
    const float* bk = (const float*)d_in[4];
    const float* Wv = (const float*)d_in[5];
    const float* bv = (const float*)d_in[6];
    const float* Wo = (const float*)d_in[7];
    const float* bo = (const float*)d_in[8];
    float* out = (float*)d_out;

    // Idempotent, not a stream op — graph-capture safe, no static guards.
    cudaFuncSetAttribute(flash_kernel,
                         cudaFuncAttributeMaxDynamicSharedMemorySize,
                         FLASH_SMEM_BYTES);

    qkv_mma_kernel<<<dim3(HID / 128, MM / 128, 3), 256>>>(X, Wq, bq, Wk, bk, Wv, bv);

    flash_kernel<<<dim3(SS / 128, BH), 256, FLASH_SMEM_BYTES>>>();

    oproj_mma_kernel<<<dim3(HID / 128, MM / 128), 256>>>(Wo, bo, out);
}

// round 8
// speedup vs baseline: 1.4192x; 1.4192x over previous
#include <cuda_runtime.h>
#include <cuda_bf16.h>
#include <math.h>
#include <stdint.h>

// Problem constants
#define BB   2
#define SS   2048
#define HH   16
#define DD   64
#define HID  1024
#define MM   (BB*SS)        // 4096
#define BH   (BB*HH)        // 32

// Scratch (device globals; allocation-guard safe)
__device__ float g_q[BH * SS * DD];   // [bh][s][d]
__device__ float g_k[BH * SS * DD];
__device__ float g_v[BH * SS * DD];
__device__ float g_ctx[MM * HID];     // [b*S+s][h*64+d]

// omega[l] = 10000^(-l/10)
__device__ __constant__ float OMEGA[10] = {
    1.0f, 0.3981071705534972f, 0.15848931924611134f, 0.0630957344480193f,
    0.025118864315095794f, 0.01f, 0.003981071705534973f, 0.001584893192461114f,
    0.000630957344480193f, 0.00025118864315095795f
};

// ----------------------------------------------------------------------------
// TF32 helpers
// ----------------------------------------------------------------------------
__device__ __forceinline__ uint32_t f2tf32(float x) {
    uint32_t r;
    asm("cvt.rna.tf32.f32 %0, %1;" : "=r"(r) : "f"(x));
    return r;
}

__device__ __forceinline__ void mma_tf32(float* d, const uint32_t* a, const uint32_t* b) {
    asm volatile(
        "mma.sync.aligned.m16n8k8.row.col.f32.tf32.tf32.f32 "
        "{%0,%1,%2,%3}, {%4,%5,%6,%7}, {%8,%9}, {%0,%1,%2,%3};"
        : "+f"(d[0]), "+f"(d[1]), "+f"(d[2]), "+f"(d[3])
        : "r"(a[0]), "r"(a[1]), "r"(a[2]), "r"(a[3]), "r"(b[0]), "r"(b[1]));
}

// ----------------------------------------------------------------------------
// QKV projection (TF32 MMA, single-buffered — R4 structure): C = X @ W + b
// -> head layout [bh][s][d], with axial RoPE fused into the epilogue (q,k).
// BM=128, BN=128, BK=16. Warp grid 4x2, warp tile 32x64.
// grid: (HID/128, MM/128, 3)
// ----------------------------------------------------------------------------
__global__ __launch_bounds__(256) void qkv_mma_kernel(
    const float* __restrict__ X,
    const float* __restrict__ Wq, const float* __restrict__ bq,
    const float* __restrict__ Wk, const float* __restrict__ bk,
    const float* __restrict__ Wv, const float* __restrict__ bv)
{
    const int z = blockIdx.z;
    const float* __restrict__ W    = (z == 0) ? Wq : (z == 1) ? Wk : Wv;
    const float* __restrict__ bias = (z == 0) ? bq : (z == 1) ? bk : bv;
    float* __restrict__ dst        = (z == 0) ? g_q : (z == 1) ? g_k : g_v;

    __shared__ uint32_t As[128][20];    // [m][k]
    __shared__ uint32_t Bs[16][136];    // [k][n]

    const int m0 = blockIdx.y * 128;
    const int n0 = blockIdx.x * 128;
    const int tid = threadIdx.x;
    const int wid = tid >> 5, lane = tid & 31;
    const int g = lane >> 2, t = lane & 3;
    const int wm = wid >> 1, wn = wid & 1;

    float acc[2][8][4];
#pragma unroll
    for (int i = 0; i < 2; i++)
#pragma unroll
        for (int j = 0; j < 8; j++)
#pragma unroll
            for (int r = 0; r < 4; r++) acc[i][j][r] = 0.0f;

    for (int k0 = 0; k0 < HID; k0 += 16) {
#pragma unroll
        for (int i = tid; i < 512; i += 256) {
            int row = i >> 2, c4 = (i & 3) * 4;
            float4 v = *(const float4*)(X + (size_t)(m0 + row) * HID + k0 + c4);
            As[row][c4 + 0] = f2tf32(v.x);
            As[row][c4 + 1] = f2tf32(v.y);
            As[row][c4 + 2] = f2tf32(v.z);
            As[row][c4 + 3] = f2tf32(v.w);
        }
#pragma unroll
        for (int i = tid; i < 512; i += 256) {
            int kk = i >> 5, n4 = (i & 31) * 4;
            float4 v = *(const float4*)(W + (size_t)(k0 + kk) * HID + n0 + n4);
            Bs[kk][n4 + 0] = f2tf32(v.x);
            Bs[kk][n4 + 1] = f2tf32(v.y);
            Bs[kk][n4 + 2] = f2tf32(v.z);
            Bs[kk][n4 + 3] = f2tf32(v.w);
        }
        __syncthreads();

#pragma unroll
        for (int ks = 0; ks < 2; ks++) {
            const int kb = ks * 8;
            uint32_t a[2][4], b[8][2];
#pragma unroll
            for (int ma = 0; ma < 2; ma++) {
                int row = wm * 32 + ma * 16 + g;
                a[ma][0] = As[row][kb + t];
                a[ma][1] = As[row + 8][kb + t];
                a[ma][2] = As[row][kb + t + 4];
                a[ma][3] = As[row + 8][kb + t + 4];
            }
#pragma unroll
            for (int na = 0; na < 8; na++) {
                int n = wn * 64 + na * 8 + g;
                b[na][0] = Bs[kb + t][n];
                b[na][1] = Bs[kb + t + 4][n];
            }
#pragma unroll
            for (int ma = 0; ma < 2; ma++)
#pragma unroll
                for (int na = 0; na < 8; na++)
                    mma_tf32(acc[ma][na], a[ma], b[na]);
        }
        __syncthreads();
    }

    // Epilogue: +bias, fused axial RoPE (q,k only), scatter to [bh][s][d]
    const bool do_rope = (z < 2);
#pragma unroll
    for (int ma = 0; ma < 2; ma++) {
#pragma unroll
        for (int na = 0; na < 8; na++) {
            int m = m0 + wm * 32 + ma * 16 + g;
            int n = n0 + wn * 64 + na * 8 + 2 * t;
            float b0 = bias[n], b1 = bias[n + 1];
            int h = n >> 6, d = n & 63;

            float y00 = acc[ma][na][0] + b0;   // row m,   col d
            float y01 = acc[ma][na][1] + b1;   // row m,   col d+1
            float y10 = acc[ma][na][2] + b0;   // row m+8
            float y11 = acc[ma][na][3] + b1;

            if (do_rope && d < 60) {
                int seg = d / 20;
                int j = d - seg * 20;              // even, [0,18]
                int l0 = (j < 10) ? j : j - 10;
                int l1 = (j + 1 < 10) ? j + 1 : j - 9;
                float om0 = OMEGA[l0], om1 = OMEGA[l1];
                {
                    int s = m & 2047;
                    int pos = (seg == 0) ? (s >> 8) : (seg == 1) ? ((s >> 4) & 15) : (s & 15);
                    float p = (float)pos;
                    float sn0, cs0, sn1, cs1;
                    sincosf(p * om0, &sn0, &cs0);
                    sincosf(p * om1, &sn1, &cs1);
                    float r0 = y00 * cs0 - y01 * sn0;
                    float r1 = y01 * cs1 + y00 * sn1;
                    y00 = r0; y01 = r1;
                }
                {
                    int s = (m + 8) & 2047;
                    int pos = (seg == 0) ? (s >> 8) : (seg == 1) ? ((s >> 4) & 15) : (s & 15);
                    float p = (float)pos;
                    float sn0, cs0, sn1, cs1;
                    sincosf(p * om0, &sn0, &cs0);
                    sincosf(p * om1, &sn1, &cs1);
                    float r0 = y10 * cs0 - y11 * sn0;
                    float r1 = y11 * cs1 + y10 * sn1;
                    y10 = r0; y11 = r1;
                }
            }
            {
                int b = m >> 11, s = m & 2047;
                float2 v = { y00, y01 };
                *(float2*)(dst + (((size_t)((b << 4) + h)) * SS + s) * DD + d) = v;
            }
            {
                int m2 = m + 8;
                int b = m2 >> 11, s = m2 & 2047;
                float2 v = { y10, y11 };
                *(float2*)(dst + (((size_t)((b << 4) + h)) * SS + s) * DD + d) = v;
            }
        }
    }
}

// ----------------------------------------------------------------------------
// Fused flash attention (R4 structure): softmax(Q K^T * 0.125) @ V -> g_ctx.
// Block = one (bh, 128-row Q tile); 8 warps x 16 rows; 64-key tiles.
// Scale 0.125 = 2^-3 folded into Q at load (exact under TF32 rounding).
// grid: (SS/128, BH), 256 threads, ~105 KB dynamic smem.
// ----------------------------------------------------------------------------
#define QS_STR 68
#define KS_STR 68
#define VS_STR 72
#define PS_STR 68
#define SM_Q 0
#define SM_K (SM_Q + 128 * QS_STR)
#define SM_V (SM_K + 64 * KS_STR)
#define SM_P (SM_V + 64 * VS_STR)
#define FLASH_SMEM_WORDS (SM_P + 128 * PS_STR)
#define FLASH_SMEM_BYTES (FLASH_SMEM_WORDS * 4)

__global__ __launch_bounds__(256) void flash_kernel()
{
    extern __shared__ uint32_t sm[];
    uint32_t* __restrict__ Qs = sm + SM_Q;
    uint32_t* __restrict__ Ks = sm + SM_K;
    uint32_t* __restrict__ Vs = sm + SM_V;
    uint32_t* __restrict__ Ps = sm + SM_P;

    const int bh = blockIdx.y;
    const int q0 = blockIdx.x * 128;
    const float* __restrict__ Q = g_q + (size_t)bh * SS * DD;
    const float* __restrict__ K = g_k + (size_t)bh * SS * DD;
    const float* __restrict__ V = g_v + (size_t)bh * SS * DD;

    const int tid = threadIdx.x;
    const int wid = tid >> 5, lane = tid & 31;
    const int g = lane >> 2, t = lane & 3;
    const int mr = wid * 16;

    // Load Q tile (128 x 64), pre-scaled by 0.125 (exact power of two)
#pragma unroll
    for (int i = tid; i < 128 * 16; i += 256) {
        int row = i >> 4, c4 = (i & 15) * 4;
        float4 v = *(const float4*)(Q + (size_t)(q0 + row) * DD + c4);
        Qs[row * QS_STR + c4 + 0] = f2tf32(0.125f * v.x);
        Qs[row * QS_STR + c4 + 1] = f2tf32(0.125f * v.y);
        Qs[row * QS_STR + c4 + 2] = f2tf32(0.125f * v.z);
        Qs[row * QS_STR + c4 + 3] = f2tf32(0.125f * v.w);
    }

    float accO[8][4];
#pragma unroll
    for (int j = 0; j < 8; j++)
#pragma unroll
        for (int r = 0; r < 4; r++) accO[j][r] = 0.0f;
    float m0 = -1e30f, m1 = -1e30f, l0 = 0.0f, l1 = 0.0f;

    for (int kt = 0; kt < SS; kt += 64) {
        __syncthreads();   // previous iteration's P.V reads done
        // Load K,V tiles (64 x 64 each)
#pragma unroll
        for (int i = tid; i < 64 * 16; i += 256) {
            int row = i >> 4, c4 = (i & 15) * 4;
            float4 kv = *(const float4*)(K + (size_t)(kt + row) * DD + c4);
            Ks[row * KS_STR + c4 + 0] = f2tf32(kv.x);
            Ks[row * KS_STR + c4 + 1] = f2tf32(kv.y);
            Ks[row * KS_STR + c4 + 2] = f2tf32(kv.z);
            Ks[row * KS_STR + c4 + 3] = f2tf32(kv.w);
            float4 vv = *(const float4*)(V + (size_t)(kt + row) * DD + c4);
            Vs[row * VS_STR + c4 + 0] = f2tf32(vv.x);
            Vs[row * VS_STR + c4 + 1] = f2tf32(vv.y);
            Vs[row * VS_STR + c4 + 2] = f2tf32(vv.z);
            Vs[row * VS_STR + c4 + 3] = f2tf32(vv.w);
        }
        __syncthreads();

        // S = (0.125 Q) K^T  (warp tile 16 x 64)
        float accS[8][4];
#pragma unroll
        for (int j = 0; j < 8; j++)
#pragma unroll
            for (int r = 0; r < 4; r++) accS[j][r] = 0.0f;

#pragma unroll
        for (int kb = 0; kb < 8; kb++) {
            uint32_t a[4];
            a[0] = Qs[(mr + g) * QS_STR + kb * 8 + t];
            a[1] = Qs[(mr + g + 8) * QS_STR + kb * 8 + t];
            a[2] = Qs[(mr + g) * QS_STR + kb * 8 + t + 4];
            a[3] = Qs[(mr + g + 8) * QS_STR + kb * 8 + t + 4];
#pragma unroll
            for (int nf = 0; nf < 8; nf++) {
                uint32_t b[2];
                b[0] = Ks[(nf * 8 + g) * KS_STR + kb * 8 + t];
                b[1] = Ks[(nf * 8 + g) * KS_STR + kb * 8 + t + 4];
                mma_tf32(accS[nf], a, b);
            }
        }

        // Online softmax (rows mr+g and mr+g+8; 4-lane quad shares a row)
        float r0 = -1e30f, r1 = -1e30f;
#pragma unroll
        for (int nf = 0; nf < 8; nf++) {
            r0 = fmaxf(r0, fmaxf(accS[nf][0], accS[nf][1]));
            r1 = fmaxf(r1, fmaxf(accS[nf][2], accS[nf][3]));
        }
        r0 = fmaxf(r0, __shfl_xor_sync(0xffffffffu, r0, 1));
        r0 = fmaxf(r0, __shfl_xor_sync(0xffffffffu, r0, 2));
        r1 = fmaxf(r1, __shfl_xor_sync(0xffffffffu, r1, 1));
        r1 = fmaxf(r1, __shfl_xor_sync(0xffffffffu, r1, 2));

        float mn0 = fmaxf(m0, r0);
        float mn1 = fmaxf(m1, r1);
        float al0 = __expf(m0 - mn0);
        float al1 = __expf(m1 - mn1);
        m0 = mn0; m1 = mn1;

        float s0 = 0.0f, s1 = 0.0f;
#pragma unroll
        for (int nf = 0; nf < 8; nf++) {
            float p00 = __expf(accS[nf][0] - m0);
            float p01 = __expf(accS[nf][1] - m0);
            float p10 = __expf(accS[nf][2] - m1);
            float p11 = __expf(accS[nf][3] - m1);
            s0 += p00 + p01;
            s1 += p10 + p11;
            int c = nf * 8 + 2 * t;
            Ps[(mr + g) * PS_STR + c]         = f2tf32(p00);
            Ps[(mr + g) * PS_STR + c + 1]     = f2tf32(p01);
            Ps[(mr + g + 8) * PS_STR + c]     = f2tf32(p10);
            Ps[(mr + g + 8) * PS_STR + c + 1] = f2tf32(p11);
        }
        s0 += __shfl_xor_sync(0xffffffffu, s0, 1);
        s0 += __shfl_xor_sync(0xffffffffu, s0, 2);
        s1 += __shfl_xor_sync(0xffffffffu, s1, 1);
        s1 += __shfl_xor_sync(0xffffffffu, s1, 2);
        l0 = l0 * al0 + s0;
        l1 = l1 * al1 + s1;

#pragma unroll
        for (int nf = 0; nf < 8; nf++) {
            accO[nf][0] *= al0;
            accO[nf][1] *= al0;
            accO[nf][2] *= al1;
            accO[nf][3] *= al1;
        }
        __syncwarp();   // P rows are warp-private

        // O += P @ V
#pragma unroll
        for (int kb = 0; kb < 8; kb++) {
            uint32_t a[4];
            a[0] = Ps[(mr + g) * PS_STR + kb * 8 + t];
            a[1] = Ps[(mr + g + 8) * PS_STR + kb * 8 + t];
            a[2] = Ps[(mr + g) * PS_STR + kb * 8 + t + 4];
            a[3] = Ps[(mr + g + 8) * PS_STR + kb * 8 + t + 4];
#pragma unroll
            for (int nf = 0; nf < 8; nf++) {
                uint32_t b[2];
                b[0] = Vs[(kb * 8 + t) * VS_STR + nf * 8 + g];
                b[1] = Vs[(kb * 8 + t + 4) * VS_STR + nf * 8 + g];
                mma_tf32(accO[nf], a, b);
            }
        }
    }

    // Epilogue: normalize and write flat ctx layout
    const float inv0 = 1.0f / l0;
    const float inv1 = 1.0f / l1;
    const int bb = bh >> 4, h = bh & 15;
    const int s0r = q0 + mr + g;
#pragma unroll
    for (int nf = 0; nf < 8; nf++) {
        int d = nf * 8 + 2 * t;
        float2 v0 = { accO[nf][0] * inv0, accO[nf][1] * inv0 };
        float2 v1 = { accO[nf][2] * inv1, accO[nf][3] * inv1 };
        *(float2*)(g_ctx + ((size_t)(bb * SS + s0r)) * HID + h * DD + d) = v0;
        *(float2*)(g_ctx + ((size_t)(bb * SS + s0r + 8)) * HID + h * DD + d) = v1;
    }
}

// ----------------------------------------------------------------------------
// Output projection (TF32 MMA, single-buffered — R4 structure).
// out = ctx @ Wo + bo. M=4096, N=1024, K=1024. grid (8,32).
// ----------------------------------------------------------------------------
__global__ __launch_bounds__(256) void oproj_mma_kernel(
    const float* __restrict__ Wo, const float* __restrict__ bo,
    float* __restrict__ out)
{
    __shared__ uint32_t As[128][20];
    __shared__ uint32_t Bs[16][136];

    const int m0 = blockIdx.y * 128;
    const int n0 = blockIdx.x * 128;
    const int tid = threadIdx.x;
    const int wid = tid >> 5, lane = tid & 31;
    const int g = lane >> 2, t = lane & 3;
    const int wm = wid >> 1, wn = wid & 1;

    float acc[2][8][4];
#pragma unroll
    for (int i = 0; i < 2; i++)
#pragma unroll
        for (int j = 0; j < 8; j++)
#pragma unroll
            for (int r = 0; r < 4; r++) acc[i][j][r] = 0.0f;

    for (int k0 = 0; k0 < HID; k0 += 16) {
#pragma unroll
        for (int i = tid; i < 512; i += 256) {
            int row = i >> 2, c4 = (i & 3) * 4;
            float4 v = *(const float4*)(g_ctx + (size_t)(m0 + row) * HID + k0 + c4);
            As[row][c4 + 0] = f2tf32(v.x);
            As[row][c4 + 1] = f2tf32(v.y);
            As[row][c4 + 2] = f2tf32(v.z);
            As[row][c4 + 3] = f2tf32(v.w);
        }
#pragma unroll
        for (int i = tid; i < 512; i += 256) {
            int kk = i >> 5, n4 = (i & 31) * 4;
            float4 v = *(const float4*)(Wo + (size_t)(k0 + kk) * HID + n0 + n4);
            Bs[kk][n4 + 0] = f2tf32(v.x);
            Bs[kk][n4 + 1] = f2tf32(v.y);
            Bs[kk][n4 + 2] = f2tf32(v.z);
            Bs[kk][n4 + 3] = f2tf32(v.w);
        }
        __syncthreads();

#pragma unroll
        for (int ks = 0; ks < 2; ks++) {
            const int kb = ks * 8;
            uint32_t a[2][4], b[8][2];
#pragma unroll
            for (int ma = 0; ma < 2; ma++) {
                int row = wm * 32 + ma * 16 + g;
                a[ma][0] = As[row][kb + t];
                a[ma][1] = As[row + 8][kb + t];
                a[ma][2] = As[row][kb + t + 4];
                a[ma][3] = As[row + 8][kb + t + 4];
            }
#pragma unroll
            for (int na = 0; na < 8; na++) {
                int n = wn * 64 + na * 8 + g;
                b[na][0] = Bs[kb + t][n];
                b[na][1] = Bs[kb + t + 4][n];
            }
#pragma unroll
            for (int ma = 0; ma < 2; ma++)
#pragma unroll
                for (int na = 0; na < 8; na++)
                    mma_tf32(acc[ma][na], a[ma], b[na]);
        }
        __syncthreads();
    }

#pragma unroll
    for (int ma = 0; ma < 2; ma++) {
#pragma unroll
        for (int na = 0; na < 8; na++) {
            int m = m0 + wm * 32 + ma * 16 + g;
            int n = n0 + wn * 64 + na * 8 + 2 * t;
            float b0 = bo[n], b1 = bo[n + 1];
            float2 v0 = { acc[ma][na][0] + b0, acc[ma][na][1] + b1 };
            float2 v1 = { acc[ma][na][2] + b0, acc[ma][na][3] + b1 };
            *(float2*)(out + (size_t)m * HID + n) = v0;
            *(float2*)(out + (size_t)(m + 8) * HID + n) = v1;
        }
    }
}

// ----------------------------------------------------------------------------
extern "C" void kernel_launch(void* const* d_in, const int* in_sizes, int n_in,
                              void* d_out, int out_size)
{
    const float* X  = (const float*)d_in[0];
    const float* Wq = (const float*)d_in[1];
    const float* bq = (const float*)d_in[2];
    const float* Wk = (const float*)d_in[3];
    const float* bk = (const float*)d_in[4];
    const float* Wv = (const float*)d_in[5];
    const float* bv = (const float*)d_in[6];
    const float* Wo = (const float*)d_in[7];
    const float* bo = (const float*)d_in[8];
    float* out = (float*)d_out;

    // Idempotent, not a stream op — graph-capture safe, no static guards.
    cudaFuncSetAttribute(flash_kernel,
                         cudaFuncAttributeMaxDynamicSharedMemorySize,
                         FLASH_SMEM_BYTES);

    qkv_mma_kernel<<<dim3(HID / 128, MM / 128, 3), 256>>>(X, Wq, bq, Wk, bk, Wv, bv);

    flash_kernel<<<dim3(SS / 128, BH), 256, FLASH_SMEM_BYTES>>>();

    oproj_mma_kernel<<<dim3(HID / 128, MM / 128), 256>>>(Wo, bo, out);
}

// round 10
// speedup vs baseline: 1.4773x; 1.0409x over previous
#include <cuda_runtime.h>
#include <cuda_bf16.h>
#include <math.h>
#include <stdint.h>

// Problem constants
#define BB   2
#define SS   2048
#define HH   16
#define DD   64
#define HID  1024
#define MM   (BB*SS)        // 4096
#define BH   (BB*HH)        // 32

// Scratch (device globals; allocation-guard safe)
__device__ float g_q[BH * SS * DD];   // [bh][s][d]
__device__ float g_k[BH * SS * DD];
__device__ float g_v[BH * SS * DD];
__device__ float g_ctx[MM * HID];     // [b*S+s][h*64+d]

// omega[l] = 10000^(-l/10)
__device__ __constant__ float OMEGA[10] = {
    1.0f, 0.3981071705534972f, 0.15848931924611134f, 0.0630957344480193f,
    0.025118864315095794f, 0.01f, 0.003981071705534973f, 0.001584893192461114f,
    0.000630957344480193f, 0.00025118864315095795f
};

// ----------------------------------------------------------------------------
// TF32 helpers
// ----------------------------------------------------------------------------
__device__ __forceinline__ uint32_t f2tf32(float x) {
    uint32_t r;
    asm("cvt.rna.tf32.f32 %0, %1;" : "=r"(r) : "f"(x));
    return r;
}

__device__ __forceinline__ void mma_tf32(float* d, const uint32_t* a, const uint32_t* b) {
    asm volatile(
        "mma.sync.aligned.m16n8k8.row.col.f32.tf32.tf32.f32 "
        "{%0,%1,%2,%3}, {%4,%5,%6,%7}, {%8,%9}, {%0,%1,%2,%3};"
        : "+f"(d[0]), "+f"(d[1]), "+f"(d[2]), "+f"(d[3])
        : "r"(a[0]), "r"(a[1]), "r"(a[2]), "r"(a[3]), "r"(b[0]), "r"(b[1]));
}

// ----------------------------------------------------------------------------
// QKV projection (TF32 MMA, DOUBLE-buffered — proven R6 structure, 237us):
// C = X @ W + b -> [bh][s][d], RoPE fused into epilogue for q,k.
// BM=128, BN=128, BK=16. Warp grid 4x2, warp tile 32x64. grid (8,32,3).
// ----------------------------------------------------------------------------
__global__ __launch_bounds__(256) void qkv_mma_kernel(
    const float* __restrict__ X,
    const float* __restrict__ Wq, const float* __restrict__ bq,
    const float* __restrict__ Wk, const float* __restrict__ bk,
    const float* __restrict__ Wv, const float* __restrict__ bv)
{
    const int z = blockIdx.z;
    const float* __restrict__ W    = (z == 0) ? Wq : (z == 1) ? Wk : Wv;
    const float* __restrict__ bias = (z == 0) ? bq : (z == 1) ? bk : bv;
    float* __restrict__ dst        = (z == 0) ? g_q : (z == 1) ? g_k : g_v;

    __shared__ uint32_t As[2][128][20];
    __shared__ uint32_t Bs[2][16][136];

    const int m0 = blockIdx.y * 128;
    const int n0 = blockIdx.x * 128;
    const int tid = threadIdx.x;
    const int wid = tid >> 5, lane = tid & 31;
    const int g = lane >> 2, t = lane & 3;
    const int wm = wid >> 1, wn = wid & 1;

    const int arow = tid >> 2,  ac4 = (tid & 3) * 4;    // + u*64 rows
    const int brow = tid >> 5,  bn4 = (tid & 31) * 4;   // + u*8 k-rows

    float acc[2][8][4];
#pragma unroll
    for (int i = 0; i < 2; i++)
#pragma unroll
        for (int j = 0; j < 8; j++)
#pragma unroll
            for (int r = 0; r < 4; r++) acc[i][j][r] = 0.0f;

    float4 ra[2], rb[2];
#pragma unroll
    for (int u = 0; u < 2; u++) {
        ra[u] = *(const float4*)(X + (size_t)(m0 + arow + u * 64) * HID + ac4);
        rb[u] = *(const float4*)(W + (size_t)(brow + u * 8) * HID + n0 + bn4);
    }
#pragma unroll
    for (int u = 0; u < 2; u++) {
        uint32_t* pa = &As[0][arow + u * 64][ac4];
        pa[0] = f2tf32(ra[u].x); pa[1] = f2tf32(ra[u].y);
        pa[2] = f2tf32(ra[u].z); pa[3] = f2tf32(ra[u].w);
        uint32_t* pb = &Bs[0][brow + u * 8][bn4];
        pb[0] = f2tf32(rb[u].x); pb[1] = f2tf32(rb[u].y);
        pb[2] = f2tf32(rb[u].z); pb[3] = f2tf32(rb[u].w);
    }
    __syncthreads();

    int buf = 0;
    for (int k0 = 0; k0 < HID; k0 += 16) {
        const bool has_next = (k0 + 16 < HID);
        if (has_next) {
#pragma unroll
            for (int u = 0; u < 2; u++) {
                ra[u] = *(const float4*)(X + (size_t)(m0 + arow + u * 64) * HID + k0 + 16 + ac4);
                rb[u] = *(const float4*)(W + (size_t)(k0 + 16 + brow + u * 8) * HID + n0 + bn4);
            }
        }

#pragma unroll
        for (int ks = 0; ks < 2; ks++) {
            const int kb = ks * 8;
            uint32_t a[2][4], b[8][2];
#pragma unroll
            for (int ma = 0; ma < 2; ma++) {
                int row = wm * 32 + ma * 16 + g;
                a[ma][0] = As[buf][row][kb + t];
                a[ma][1] = As[buf][row + 8][kb + t];
                a[ma][2] = As[buf][row][kb + t + 4];
                a[ma][3] = As[buf][row + 8][kb + t + 4];
            }
#pragma unroll
            for (int na = 0; na < 8; na++) {
                int n = wn * 64 + na * 8 + g;
                b[na][0] = Bs[buf][kb + t][n];
                b[na][1] = Bs[buf][kb + t + 4][n];
            }
#pragma unroll
            for (int ma = 0; ma < 2; ma++)
#pragma unroll
                for (int na = 0; na < 8; na++)
                    mma_tf32(acc[ma][na], a[ma], b[na]);
        }

        if (has_next) {
            const int nb = buf ^ 1;
#pragma unroll
            for (int u = 0; u < 2; u++) {
                uint32_t* pa = &As[nb][arow + u * 64][ac4];
                pa[0] = f2tf32(ra[u].x); pa[1] = f2tf32(ra[u].y);
                pa[2] = f2tf32(ra[u].z); pa[3] = f2tf32(ra[u].w);
                uint32_t* pb = &Bs[nb][brow + u * 8][bn4];
                pb[0] = f2tf32(rb[u].x); pb[1] = f2tf32(rb[u].y);
                pb[2] = f2tf32(rb[u].z); pb[3] = f2tf32(rb[u].w);
            }
        }
        __syncthreads();
        buf ^= 1;
    }

    // Epilogue: +bias, fused axial RoPE (q,k only), scatter to [bh][s][d]
    const bool do_rope = (z < 2);
#pragma unroll
    for (int ma = 0; ma < 2; ma++) {
#pragma unroll
        for (int na = 0; na < 8; na++) {
            int m = m0 + wm * 32 + ma * 16 + g;
            int n = n0 + wn * 64 + na * 8 + 2 * t;
            float b0 = bias[n], b1 = bias[n + 1];
            int h = n >> 6, d = n & 63;

            float y00 = acc[ma][na][0] + b0;
            float y01 = acc[ma][na][1] + b1;
            float y10 = acc[ma][na][2] + b0;
            float y11 = acc[ma][na][3] + b1;

            if (do_rope && d < 60) {
                int seg = d / 20;
                int j = d - seg * 20;
                int l0 = (j < 10) ? j : j - 10;
                int l1 = (j + 1 < 10) ? j + 1 : j - 9;
                float om0 = OMEGA[l0], om1 = OMEGA[l1];
                {
                    int s = m & 2047;
                    int pos = (seg == 0) ? (s >> 8) : (seg == 1) ? ((s >> 4) & 15) : (s & 15);
                    float p = (float)pos;
                    float sn0, cs0, sn1, cs1;
                    sincosf(p * om0, &sn0, &cs0);
                    sincosf(p * om1, &sn1, &cs1);
                    float r0 = y00 * cs0 - y01 * sn0;
                    float r1 = y01 * cs1 + y00 * sn1;
                    y00 = r0; y01 = r1;
                }
                {
                    int s = (m + 8) & 2047;
                    int pos = (seg == 0) ? (s >> 8) : (seg == 1) ? ((s >> 4) & 15) : (s & 15);
                    float p = (float)pos;
                    float sn0, cs0, sn1, cs1;
                    sincosf(p * om0, &sn0, &cs0);
                    sincosf(p * om1, &sn1, &cs1);
                    float r0 = y10 * cs0 - y11 * sn0;
                    float r1 = y11 * cs1 + y10 * sn1;
                    y10 = r0; y11 = r1;
                }
            }
            {
                int b = m >> 11, s = m & 2047;
                float2 v = { y00, y01 };
                *(float2*)(dst + (((size_t)((b << 4) + h)) * SS + s) * DD + d) = v;
            }
            {
                int m2 = m + 8;
                int b = m2 >> 11, s = m2 & 2047;
                float2 v = { y10, y11 };
                *(float2*)(dst + (((size_t)((b << 4) + h)) * SS + s) * DD + d) = v;
            }
        }
    }
}

// ----------------------------------------------------------------------------
// Fused flash attention (SINGLE-buffered — proven R4 structure; 105 KB smem
// keeps 2 CTAs/SM): softmax(Q K^T * 0.125) @ V -> g_ctx (flat layout).
// Block = one (bh, 128-row Q tile); 8 warps x 16 rows; 64-key tiles.
// Scale 0.125 = 2^-3 folded into Q at load (exact under TF32 rounding).
// grid: (SS/128, BH), 256 threads.
// ----------------------------------------------------------------------------
#define QS_STR 68
#define KS_STR 68
#define VS_STR 72
#define PS_STR 68
#define SM_Q 0
#define SM_K (SM_Q + 128 * QS_STR)
#define SM_V (SM_K + 64 * KS_STR)
#define SM_P (SM_V + 64 * VS_STR)
#define FLASH_SMEM_WORDS (SM_P + 128 * PS_STR)
#define FLASH_SMEM_BYTES (FLASH_SMEM_WORDS * 4)

__global__ __launch_bounds__(256) void flash_kernel()
{
    extern __shared__ uint32_t sm[];
    uint32_t* __restrict__ Qs = sm + SM_Q;
    uint32_t* __restrict__ Ks = sm + SM_K;
    uint32_t* __restrict__ Vs = sm + SM_V;
    uint32_t* __restrict__ Ps = sm + SM_P;

    const int bh = blockIdx.y;
    const int q0 = blockIdx.x * 128;
    const float* __restrict__ Q = g_q + (size_t)bh * SS * DD;
    const float* __restrict__ K = g_k + (size_t)bh * SS * DD;
    const float* __restrict__ V = g_v + (size_t)bh * SS * DD;

    const int tid = threadIdx.x;
    const int wid = tid >> 5, lane = tid & 31;
    const int g = lane >> 2, t = lane & 3;
    const int mr = wid * 16;

    // Load Q tile (128 x 64), pre-scaled by 0.125 (exact power of two)
#pragma unroll
    for (int i = tid; i < 128 * 16; i += 256) {
        int row = i >> 4, c4 = (i & 15) * 4;
        float4 v = *(const float4*)(Q + (size_t)(q0 + row) * DD + c4);
        Qs[row * QS_STR + c4 + 0] = f2tf32(0.125f * v.x);
        Qs[row * QS_STR + c4 + 1] = f2tf32(0.125f * v.y);
        Qs[row * QS_STR + c4 + 2] = f2tf32(0.125f * v.z);
        Qs[row * QS_STR + c4 + 3] = f2tf32(0.125f * v.w);
    }

    float accO[8][4];
#pragma unroll
    for (int j = 0; j < 8; j++)
#pragma unroll
        for (int r = 0; r < 4; r++) accO[j][r] = 0.0f;
    float m0 = -1e30f, m1 = -1e30f, l0 = 0.0f, l1 = 0.0f;

    for (int kt = 0; kt < SS; kt += 64) {
        __syncthreads();   // previous iteration's P.V reads done
#pragma unroll
        for (int i = tid; i < 64 * 16; i += 256) {
            int row = i >> 4, c4 = (i & 15) * 4;
            float4 kv = *(const float4*)(K + (size_t)(kt + row) * DD + c4);
            Ks[row * KS_STR + c4 + 0] = f2tf32(kv.x);
            Ks[row * KS_STR + c4 + 1] = f2tf32(kv.y);
            Ks[row * KS_STR + c4 + 2] = f2tf32(kv.z);
            Ks[row * KS_STR + c4 + 3] = f2tf32(kv.w);
            float4 vv = *(const float4*)(V + (size_t)(kt + row) * DD + c4);
            Vs[row * VS_STR + c4 + 0] = f2tf32(vv.x);
            Vs[row * VS_STR + c4 + 1] = f2tf32(vv.y);
            Vs[row * VS_STR + c4 + 2] = f2tf32(vv.z);
            Vs[row * VS_STR + c4 + 3] = f2tf32(vv.w);
        }
        __syncthreads();

        // S = (0.125 Q) K^T  (warp tile 16 x 64)
        float accS[8][4];
#pragma unroll
        for (int j = 0; j < 8; j++)
#pragma unroll
            for (int r = 0; r < 4; r++) accS[j][r] = 0.0f;

#pragma unroll
        for (int kb = 0; kb < 8; kb++) {
            uint32_t a[4];
            a[0] = Qs[(mr + g) * QS_STR + kb * 8 + t];
            a[1] = Qs[(mr + g + 8) * QS_STR + kb * 8 + t];
            a[2] = Qs[(mr + g) * QS_STR + kb * 8 + t + 4];
            a[3] = Qs[(mr + g + 8) * QS_STR + kb * 8 + t + 4];
#pragma unroll
            for (int nf = 0; nf < 8; nf++) {
                uint32_t b[2];
                b[0] = Ks[(nf * 8 + g) * KS_STR + kb * 8 + t];
                b[1] = Ks[(nf * 8 + g) * KS_STR + kb * 8 + t + 4];
                mma_tf32(accS[nf], a, b);
            }
        }

        // Online softmax (rows mr+g and mr+g+8; 4-lane quad shares a row)
        float r0 = -1e30f, r1 = -1e30f;
#pragma unroll
        for (int nf = 0; nf < 8; nf++) {
            r0 = fmaxf(r0, fmaxf(accS[nf][0], accS[nf][1]));
            r1 = fmaxf(r1, fmaxf(accS[nf][2], accS[nf][3]));
        }
        r0 = fmaxf(r0, __shfl_xor_sync(0xffffffffu, r0, 1));
        r0 = fmaxf(r0, __shfl_xor_sync(0xffffffffu, r0, 2));
        r1 = fmaxf(r1, __shfl_xor_sync(0xffffffffu, r1, 1));
        r1 = fmaxf(r1, __shfl_xor_sync(0xffffffffu, r1, 2));

        float mn0 = fmaxf(m0, r0);
        float mn1 = fmaxf(m1, r1);
        float al0 = __expf(m0 - mn0);
        float al1 = __expf(m1 - mn1);
        m0 = mn0; m1 = mn1;

        float s0 = 0.0f, s1 = 0.0f;
#pragma unroll
        for (int nf = 0; nf < 8; nf++) {
            float p00 = __expf(accS[nf][0] - m0);
            float p01 = __expf(accS[nf][1] - m0);
            float p10 = __expf(accS[nf][2] - m1);
            float p11 = __expf(accS[nf][3] - m1);
            s0 += p00 + p01;
            s1 += p10 + p11;
            int c = nf * 8 + 2 * t;
            Ps[(mr + g) * PS_STR + c]         = f2tf32(p00);
            Ps[(mr + g) * PS_STR + c + 1]     = f2tf32(p01);
            Ps[(mr + g + 8) * PS_STR + c]     = f2tf32(p10);
            Ps[(mr + g + 8) * PS_STR + c + 1] = f2tf32(p11);
        }
        s0 += __shfl_xor_sync(0xffffffffu, s0, 1);
        s0 += __shfl_xor_sync(0xffffffffu, s0, 2);
        s1 += __shfl_xor_sync(0xffffffffu, s1, 1);
        s1 += __shfl_xor_sync(0xffffffffu, s1, 2);
        l0 = l0 * al0 + s0;
        l1 = l1 * al1 + s1;

#pragma unroll
        for (int nf = 0; nf < 8; nf++) {
            accO[nf][0] *= al0;
            accO[nf][1] *= al0;
            accO[nf][2] *= al1;
            accO[nf][3] *= al1;
        }
        __syncwarp();   // P rows are warp-private

        // O += P @ V
#pragma unroll
        for (int kb = 0; kb < 8; kb++) {
            uint32_t a[4];
            a[0] = Ps[(mr + g) * PS_STR + kb * 8 + t];
            a[1] = Ps[(mr + g + 8) * PS_STR + kb * 8 + t];
            a[2] = Ps[(mr + g) * PS_STR + kb * 8 + t + 4];
            a[3] = Ps[(mr + g + 8) * PS_STR + kb * 8 + t + 4];
#pragma unroll
            for (int nf = 0; nf < 8; nf++) {
                uint32_t b[2];
                b[0] = Vs[(kb * 8 + t) * VS_STR + nf * 8 + g];
                b[1] = Vs[(kb * 8 + t + 4) * VS_STR + nf * 8 + g];
                mma_tf32(accO[nf], a, b);
            }
        }
    }

    // Epilogue: normalize and write flat ctx layout
    const float inv0 = 1.0f / l0;
    const float inv1 = 1.0f / l1;
    const int bb = bh >> 4, h = bh & 15;
    const int s0r = q0 + mr + g;
#pragma unroll
    for (int nf = 0; nf < 8; nf++) {
        int d = nf * 8 + 2 * t;
        float2 v0 = { accO[nf][0] * inv0, accO[nf][1] * inv0 };
        float2 v1 = { accO[nf][2] * inv1, accO[nf][3] * inv1 };
        *(float2*)(g_ctx + ((size_t)(bb * SS + s0r)) * HID + h * DD + d) = v0;
        *(float2*)(g_ctx + ((size_t)(bb * SS + s0r + 8)) * HID + h * DD + d) = v1;
    }
}

// ----------------------------------------------------------------------------
// Output projection (TF32 MMA, DOUBLE-buffered — R6 structure).
// out = ctx @ Wo + bo. M=4096, N=1024, K=1024. grid (8,32).
// ----------------------------------------------------------------------------
__global__ __launch_bounds__(256) void oproj_mma_kernel(
    const float* __restrict__ Wo, const float* __restrict__ bo,
    float* __restrict__ out)
{
    __shared__ uint32_t As[2][128][20];
    __shared__ uint32_t Bs[2][16][136];

    const int m0 = blockIdx.y * 128;
    const int n0 = blockIdx.x * 128;
    const int tid = threadIdx.x;
    const int wid = tid >> 5, lane = tid & 31;
    const int g = lane >> 2, t = lane & 3;
    const int wm = wid >> 1, wn = wid & 1;

    const int arow = tid >> 2,  ac4 = (tid & 3) * 4;
    const int brow = tid >> 5,  bn4 = (tid & 31) * 4;

    float acc[2][8][4];
#pragma unroll
    for (int i = 0; i < 2; i++)
#pragma unroll
        for (int j = 0; j < 8; j++)
#pragma unroll
            for (int r = 0; r < 4; r++) acc[i][j][r] = 0.0f;

    float4 ra[2], rb[2];
#pragma unroll
    for (int u = 0; u < 2; u++) {
        ra[u] = *(const float4*)(g_ctx + (size_t)(m0 + arow + u * 64) * HID + ac4);
        rb[u] = *(const float4*)(Wo + (size_t)(brow + u * 8) * HID + n0 + bn4);
    }
#pragma unroll
    for (int u = 0; u < 2; u++) {
        uint32_t* pa = &As[0][arow + u * 64][ac4];
        pa[0] = f2tf32(ra[u].x); pa[1] = f2tf32(ra[u].y);
        pa[2] = f2tf32(ra[u].z); pa[3] = f2tf32(ra[u].w);
        uint32_t* pb = &Bs[0][brow + u * 8][bn4];
        pb[0] = f2tf32(rb[u].x); pb[1] = f2tf32(rb[u].y);
        pb[2] = f2tf32(rb[u].z); pb[3] = f2tf32(rb[u].w);
    }
    __syncthreads();

    int buf = 0;
    for (int k0 = 0; k0 < HID; k0 += 16) {
        const bool has_next = (k0 + 16 < HID);
        if (has_next) {
#pragma unroll
            for (int u = 0; u < 2; u++) {
                ra[u] = *(const float4*)(g_ctx + (size_t)(m0 + arow + u * 64) * HID + k0 + 16 + ac4);
                rb[u] = *(const float4*)(Wo + (size_t)(k0 + 16 + brow + u * 8) * HID + n0 + bn4);
            }
        }

#pragma unroll
        for (int ks = 0; ks < 2; ks++) {
            const int kb = ks * 8;
            uint32_t a[2][4], b[8][2];
#pragma unroll
            for (int ma = 0; ma < 2; ma++) {
                int row = wm * 32 + ma * 16 + g;
                a[ma][0] = As[buf][row][kb + t];
                a[ma][1] = As[buf][row + 8][kb + t];
                a[ma][2] = As[buf][row][kb + t + 4];
                a[ma][3] = As[buf][row + 8][kb + t + 4];
            }
#pragma unroll
            for (int na = 0; na < 8; na++) {
                int n = wn * 64 + na * 8 + g;
                b[na][0] = Bs[buf][kb + t][n];
                b[na][1] = Bs[buf][kb + t + 4][n];
            }
#pragma unroll
            for (int ma = 0; ma < 2; ma++)
#pragma unroll
                for (int na = 0; na < 8; na++)
                    mma_tf32(acc[ma][na], a[ma], b[na]);
        }

        if (has_next) {
            const int nb = buf ^ 1;
#pragma unroll
            for (int u = 0; u < 2; u++) {
                uint32_t* pa = &As[nb][arow + u * 64][ac4];
                pa[0] = f2tf32(ra[u].x); pa[1] = f2tf32(ra[u].y);
                pa[2] = f2tf32(ra[u].z); pa[3] = f2tf32(ra[u].w);
                uint32_t* pb = &Bs[nb][brow + u * 8][bn4];
                pb[0] = f2tf32(rb[u].x); pb[1] = f2tf32(rb[u].y);
                pb[2] = f2tf32(rb[u].z); pb[3] = f2tf32(rb[u].w);
            }
        }
        __syncthreads();
        buf ^= 1;
    }

#pragma unroll
    for (int ma = 0; ma < 2; ma++) {
#pragma unroll
        for (int na = 0; na < 8; na++) {
            int m = m0 + wm * 32 + ma * 16 + g;
            int n = n0 + wn * 64 + na * 8 + 2 * t;
            float b0 = bo[n], b1 = bo[n + 1];
            float2 v0 = { acc[ma][na][0] + b0, acc[ma][na][1] + b1 };
            float2 v1 = { acc[ma][na][2] + b0, acc[ma][na][3] + b1 };
            *(float2*)(out + (size_t)m * HID + n) = v0;
            *(float2*)(out + (size_t)(m + 8) * HID + n) = v1;
        }
    }
}

// ----------------------------------------------------------------------------
extern "C" void kernel_launch(void* const* d_in, const int* in_sizes, int n_in,
                              void* d_out, int out_size)
{
    const float* X  = (const float*)d_in[0];
    const float* Wq = (const float*)d_in[1];
    const float* bq = (const float*)d_in[2];
    const float* Wk = (const float*)d_in[3];
    const float* bk = (const float*)d_in[4];
    const float* Wv = (const float*)d_in[5];
    const float* bv = (const float*)d_in[6];
    const float* Wo = (const float*)d_in[7];
    const float* bo = (const float*)d_in[8];
    float* out = (float*)d_out;

    // Idempotent, not a stream op — graph-capture safe, no static guards.
    cudaFuncSetAttribute(flash_kernel,
                         cudaFuncAttributeMaxDynamicSharedMemorySize,
                         FLASH_SMEM_BYTES);

    qkv_mma_kernel<<<dim3(HID / 128, MM / 128, 3), 256>>>(X, Wq, bq, Wk, bk, Wv, bv);

    flash_kernel<<<dim3(SS / 128, BH), 256, FLASH_SMEM_BYTES>>>();

    oproj_mma_kernel<<<dim3(HID / 128, MM / 128), 256>>>(Wo, bo, out);
}

// round 11
// speedup vs baseline: 1.5445x; 1.0455x over previous
#include <cuda_runtime.h>
#include <cuda_bf16.h>
#include <math.h>
#include <stdint.h>

// Problem constants
#define BB   2
#define SS   2048
#define HH   16
#define DD   64
#define HID  1024
#define MM   (BB*SS)        // 4096
#define BH   (BB*HH)        // 32

// Scratch (device globals; allocation-guard safe)
__device__ float g_q[BH * SS * DD];   // [bh][s][d]
__device__ float g_k[BH * SS * DD];
__device__ float g_v[BH * SS * DD];
__device__ float g_ctx[MM * HID];     // [b*S+s][h*64+d]

// omega[l] = 10000^(-l/10)
__device__ __constant__ float OMEGA[10] = {
    1.0f, 0.3981071705534972f, 0.15848931924611134f, 0.0630957344480193f,
    0.025118864315095794f, 0.01f, 0.003981071705534973f, 0.001584893192461114f,
    0.000630957344480193f, 0.00025118864315095795f
};

// ----------------------------------------------------------------------------
// TF32 helpers
// ----------------------------------------------------------------------------
__device__ __forceinline__ uint32_t f2tf32(float x) {
    uint32_t r;
    asm("cvt.rna.tf32.f32 %0, %1;" : "=r"(r) : "f"(x));
    return r;
}

__device__ __forceinline__ void mma_tf32(float* d, const uint32_t* a, const uint32_t* b) {
    asm volatile(
        "mma.sync.aligned.m16n8k8.row.col.f32.tf32.tf32.f32 "
        "{%0,%1,%2,%3}, {%4,%5,%6,%7}, {%8,%9}, {%0,%1,%2,%3};"
        : "+f"(d[0]), "+f"(d[1]), "+f"(d[2]), "+f"(d[3])
        : "r"(a[0]), "r"(a[1]), "r"(a[2]), "r"(a[3]), "r"(b[0]), "r"(b[1]));
}

// ----------------------------------------------------------------------------
// QKV projection (TF32 MMA, DOUBLE-buffered — proven, 237us): C = X @ W + b
// -> [bh][s][d], RoPE fused into epilogue for q,k.
// BM=128, BN=128, BK=16. Warp grid 4x2, warp tile 32x64. grid (8,32,3).
// ----------------------------------------------------------------------------
__global__ __launch_bounds__(256) void qkv_mma_kernel(
    const float* __restrict__ X,
    const float* __restrict__ Wq, const float* __restrict__ bq,
    const float* __restrict__ Wk, const float* __restrict__ bk,
    const float* __restrict__ Wv, const float* __restrict__ bv)
{
    const int z = blockIdx.z;
    const float* __restrict__ W    = (z == 0) ? Wq : (z == 1) ? Wk : Wv;
    const float* __restrict__ bias = (z == 0) ? bq : (z == 1) ? bk : bv;
    float* __restrict__ dst        = (z == 0) ? g_q : (z == 1) ? g_k : g_v;

    __shared__ uint32_t As[2][128][20];
    __shared__ uint32_t Bs[2][16][136];

    const int m0 = blockIdx.y * 128;
    const int n0 = blockIdx.x * 128;
    const int tid = threadIdx.x;
    const int wid = tid >> 5, lane = tid & 31;
    const int g = lane >> 2, t = lane & 3;
    const int wm = wid >> 1, wn = wid & 1;

    const int arow = tid >> 2,  ac4 = (tid & 3) * 4;    // + u*64 rows
    const int brow = tid >> 5,  bn4 = (tid & 31) * 4;   // + u*8 k-rows

    float acc[2][8][4];
#pragma unroll
    for (int i = 0; i < 2; i++)
#pragma unroll
        for (int j = 0; j < 8; j++)
#pragma unroll
            for (int r = 0; r < 4; r++) acc[i][j][r] = 0.0f;

    float4 ra[2], rb[2];
#pragma unroll
    for (int u = 0; u < 2; u++) {
        ra[u] = *(const float4*)(X + (size_t)(m0 + arow + u * 64) * HID + ac4);
        rb[u] = *(const float4*)(W + (size_t)(brow + u * 8) * HID + n0 + bn4);
    }
#pragma unroll
    for (int u = 0; u < 2; u++) {
        uint32_t* pa = &As[0][arow + u * 64][ac4];
        pa[0] = f2tf32(ra[u].x); pa[1] = f2tf32(ra[u].y);
        pa[2] = f2tf32(ra[u].z); pa[3] = f2tf32(ra[u].w);
        uint32_t* pb = &Bs[0][brow + u * 8][bn4];
        pb[0] = f2tf32(rb[u].x); pb[1] = f2tf32(rb[u].y);
        pb[2] = f2tf32(rb[u].z); pb[3] = f2tf32(rb[u].w);
    }
    __syncthreads();

    int buf = 0;
    for (int k0 = 0; k0 < HID; k0 += 16) {
        const bool has_next = (k0 + 16 < HID);
        if (has_next) {
#pragma unroll
            for (int u = 0; u < 2; u++) {
                ra[u] = *(const float4*)(X + (size_t)(m0 + arow + u * 64) * HID + k0 + 16 + ac4);
                rb[u] = *(const float4*)(W + (size_t)(k0 + 16 + brow + u * 8) * HID + n0 + bn4);
            }
        }

#pragma unroll
        for (int ks = 0; ks < 2; ks++) {
            const int kb = ks * 8;
            uint32_t a[2][4], b[8][2];
#pragma unroll
            for (int ma = 0; ma < 2; ma++) {
                int row = wm * 32 + ma * 16 + g;
                a[ma][0] = As[buf][row][kb + t];
                a[ma][1] = As[buf][row + 8][kb + t];
                a[ma][2] = As[buf][row][kb + t + 4];
                a[ma][3] = As[buf][row + 8][kb + t + 4];
            }
#pragma unroll
            for (int na = 0; na < 8; na++) {
                int n = wn * 64 + na * 8 + g;
                b[na][0] = Bs[buf][kb + t][n];
                b[na][1] = Bs[buf][kb + t + 4][n];
            }
#pragma unroll
            for (int ma = 0; ma < 2; ma++)
#pragma unroll
                for (int na = 0; na < 8; na++)
                    mma_tf32(acc[ma][na], a[ma], b[na]);
        }

        if (has_next) {
            const int nb = buf ^ 1;
#pragma unroll
            for (int u = 0; u < 2; u++) {
                uint32_t* pa = &As[nb][arow + u * 64][ac4];
                pa[0] = f2tf32(ra[u].x); pa[1] = f2tf32(ra[u].y);
                pa[2] = f2tf32(ra[u].z); pa[3] = f2tf32(ra[u].w);
                uint32_t* pb = &Bs[nb][brow + u * 8][bn4];
                pb[0] = f2tf32(rb[u].x); pb[1] = f2tf32(rb[u].y);
                pb[2] = f2tf32(rb[u].z); pb[3] = f2tf32(rb[u].w);
            }
        }
        __syncthreads();
        buf ^= 1;
    }

    // Epilogue: +bias, fused axial RoPE (q,k only), scatter to [bh][s][d]
    const bool do_rope = (z < 2);
#pragma unroll
    for (int ma = 0; ma < 2; ma++) {
#pragma unroll
        for (int na = 0; na < 8; na++) {
            int m = m0 + wm * 32 + ma * 16 + g;
            int n = n0 + wn * 64 + na * 8 + 2 * t;
            float b0 = bias[n], b1 = bias[n + 1];
            int h = n >> 6, d = n & 63;

            float y00 = acc[ma][na][0] + b0;
            float y01 = acc[ma][na][1] + b1;
            float y10 = acc[ma][na][2] + b0;
            float y11 = acc[ma][na][3] + b1;

            if (do_rope && d < 60) {
                int seg = d / 20;
                int j = d - seg * 20;
                int l0 = (j < 10) ? j : j - 10;
                int l1 = (j + 1 < 10) ? j + 1 : j - 9;
                float om0 = OMEGA[l0], om1 = OMEGA[l1];
                {
                    int s = m & 2047;
                    int pos = (seg == 0) ? (s >> 8) : (seg == 1) ? ((s >> 4) & 15) : (s & 15);
                    float p = (float)pos;
                    float sn0, cs0, sn1, cs1;
                    sincosf(p * om0, &sn0, &cs0);
                    sincosf(p * om1, &sn1, &cs1);
                    float r0 = y00 * cs0 - y01 * sn0;
                    float r1 = y01 * cs1 + y00 * sn1;
                    y00 = r0; y01 = r1;
                }
                {
                    int s = (m + 8) & 2047;
                    int pos = (seg == 0) ? (s >> 8) : (seg == 1) ? ((s >> 4) & 15) : (s & 15);
                    float p = (float)pos;
                    float sn0, cs0, sn1, cs1;
                    sincosf(p * om0, &sn0, &cs0);
                    sincosf(p * om1, &sn1, &cs1);
                    float r0 = y10 * cs0 - y11 * sn0;
                    float r1 = y11 * cs1 + y10 * sn1;
                    y10 = r0; y11 = r1;
                }
            }
            {
                int b = m >> 11, s = m & 2047;
                float2 v = { y00, y01 };
                *(float2*)(dst + (((size_t)((b << 4) + h)) * SS + s) * DD + d) = v;
            }
            {
                int m2 = m + 8;
                int b = m2 >> 11, s = m2 & 2047;
                float2 v = { y10, y11 };
                *(float2*)(dst + (((size_t)((b << 4) + h)) * SS + s) * DD + d) = v;
            }
        }
    }
}

// ----------------------------------------------------------------------------
// Fused flash attention: softmax(Q K^T * 0.125) @ V -> g_ctx (flat layout).
// SINGLE smem buffer (105 KB -> 2 CTAs/SM preserved) + REGISTER-prefetched
// K/V: loop = { sync; STS(prefetched); sync; LDG(next)->regs; compute }.
// The LDG's ~600cyc latency hides under the compute phase instead of being
// exposed inside the staging window.
// Block = one (bh, 128-row Q tile); 8 warps x 16 rows; 64-key tiles.
// Scale 0.125 = 2^-3 folded into Q at load (exact under TF32 rounding).
// grid: (SS/128, BH), 256 threads.
// ----------------------------------------------------------------------------
#define QS_STR 68
#define KS_STR 68
#define VS_STR 72
#define PS_STR 68
#define SM_Q 0
#define SM_K (SM_Q + 128 * QS_STR)
#define SM_V (SM_K + 64 * KS_STR)
#define SM_P (SM_V + 64 * VS_STR)
#define FLASH_SMEM_WORDS (SM_P + 128 * PS_STR)
#define FLASH_SMEM_BYTES (FLASH_SMEM_WORDS * 4)

__global__ __launch_bounds__(256, 2) void flash_kernel()
{
    extern __shared__ uint32_t sm[];
    uint32_t* __restrict__ Qs = sm + SM_Q;
    uint32_t* __restrict__ Ks = sm + SM_K;
    uint32_t* __restrict__ Vs = sm + SM_V;
    uint32_t* __restrict__ Ps = sm + SM_P;

    const int bh = blockIdx.y;
    const int q0 = blockIdx.x * 128;
    const float* __restrict__ Q = g_q + (size_t)bh * SS * DD;
    const float* __restrict__ K = g_k + (size_t)bh * SS * DD;
    const float* __restrict__ V = g_v + (size_t)bh * SS * DD;

    const int tid = threadIdx.x;
    const int wid = tid >> 5, lane = tid & 31;
    const int g = lane >> 2, t = lane & 3;
    const int mr = wid * 16;

    // K/V staging geometry: thread covers rows srow+16u (u<4), cols sc4..+3
    const int srow = tid >> 4, sc4 = (tid & 15) * 4;

    // Load Q tile (128 x 64), pre-scaled by 0.125 (exact power of two)
#pragma unroll
    for (int i = tid; i < 128 * 16; i += 256) {
        int row = i >> 4, c4 = (i & 15) * 4;
        float4 v = *(const float4*)(Q + (size_t)(q0 + row) * DD + c4);
        Qs[row * QS_STR + c4 + 0] = f2tf32(0.125f * v.x);
        Qs[row * QS_STR + c4 + 1] = f2tf32(0.125f * v.y);
        Qs[row * QS_STR + c4 + 2] = f2tf32(0.125f * v.z);
        Qs[row * QS_STR + c4 + 3] = f2tf32(0.125f * v.w);
    }

    // Prefetch K/V tile 0 into registers
    float4 rk[4], rv[4];
#pragma unroll
    for (int u = 0; u < 4; u++) {
        rk[u] = *(const float4*)(K + (size_t)(srow + u * 16) * DD + sc4);
        rv[u] = *(const float4*)(V + (size_t)(srow + u * 16) * DD + sc4);
    }

    float accO[8][4];
#pragma unroll
    for (int j = 0; j < 8; j++)
#pragma unroll
        for (int r = 0; r < 4; r++) accO[j][r] = 0.0f;
    float m0 = -1e30f, m1 = -1e30f, l0 = 0.0f, l1 = 0.0f;

    for (int kt = 0; kt < SS; kt += 64) {
        __syncthreads();   // all reads of Ks/Vs from previous iteration done
        // Commit prefetched registers to smem
#pragma unroll
        for (int u = 0; u < 4; u++) {
            uint32_t* pk = Ks + (srow + u * 16) * KS_STR + sc4;
            pk[0] = f2tf32(rk[u].x); pk[1] = f2tf32(rk[u].y);
            pk[2] = f2tf32(rk[u].z); pk[3] = f2tf32(rk[u].w);
            uint32_t* pv = Vs + (srow + u * 16) * VS_STR + sc4;
            pv[0] = f2tf32(rv[u].x); pv[1] = f2tf32(rv[u].y);
            pv[2] = f2tf32(rv[u].z); pv[3] = f2tf32(rv[u].w);
        }
        __syncthreads();

        // Issue next tile's loads NOW — latency hides under the compute below
        const bool has_next = (kt + 64 < SS);
        if (has_next) {
#pragma unroll
            for (int u = 0; u < 4; u++) {
                rk[u] = *(const float4*)(K + (size_t)(kt + 64 + srow + u * 16) * DD + sc4);
                rv[u] = *(const float4*)(V + (size_t)(kt + 64 + srow + u * 16) * DD + sc4);
            }
        }

        // S = (0.125 Q) K^T  (warp tile 16 x 64)
        float accS[8][4];
#pragma unroll
        for (int j = 0; j < 8; j++)
#pragma unroll
            for (int r = 0; r < 4; r++) accS[j][r] = 0.0f;

#pragma unroll
        for (int kb = 0; kb < 8; kb++) {
            uint32_t a[4];
            a[0] = Qs[(mr + g) * QS_STR + kb * 8 + t];
            a[1] = Qs[(mr + g + 8) * QS_STR + kb * 8 + t];
            a[2] = Qs[(mr + g) * QS_STR + kb * 8 + t + 4];
            a[3] = Qs[(mr + g + 8) * QS_STR + kb * 8 + t + 4];
#pragma unroll
            for (int nf = 0; nf < 8; nf++) {
                uint32_t b[2];
                b[0] = Ks[(nf * 8 + g) * KS_STR + kb * 8 + t];
                b[1] = Ks[(nf * 8 + g) * KS_STR + kb * 8 + t + 4];
                mma_tf32(accS[nf], a, b);
            }
        }

        // Online softmax (rows mr+g and mr+g+8; 4-lane quad shares a row)
        float r0 = -1e30f, r1 = -1e30f;
#pragma unroll
        for (int nf = 0; nf < 8; nf++) {
            r0 = fmaxf(r0, fmaxf(accS[nf][0], accS[nf][1]));
            r1 = fmaxf(r1, fmaxf(accS[nf][2], accS[nf][3]));
        }
        r0 = fmaxf(r0, __shfl_xor_sync(0xffffffffu, r0, 1));
        r0 = fmaxf(r0, __shfl_xor_sync(0xffffffffu, r0, 2));
        r1 = fmaxf(r1, __shfl_xor_sync(0xffffffffu, r1, 1));
        r1 = fmaxf(r1, __shfl_xor_sync(0xffffffffu, r1, 2));

        float mn0 = fmaxf(m0, r0);
        float mn1 = fmaxf(m1, r1);
        float al0 = __expf(m0 - mn0);
        float al1 = __expf(m1 - mn1);
        m0 = mn0; m1 = mn1;

        float s0 = 0.0f, s1 = 0.0f;
#pragma unroll
        for (int nf = 0; nf < 8; nf++) {
            float p00 = __expf(accS[nf][0] - m0);
            float p01 = __expf(accS[nf][1] - m0);
            float p10 = __expf(accS[nf][2] - m1);
            float p11 = __expf(accS[nf][3] - m1);
            s0 += p00 + p01;
            s1 += p10 + p11;
            int c = nf * 8 + 2 * t;
            Ps[(mr + g) * PS_STR + c]         = f2tf32(p00);
            Ps[(mr + g) * PS_STR + c + 1]     = f2tf32(p01);
            Ps[(mr + g + 8) * PS_STR + c]     = f2tf32(p10);
            Ps[(mr + g + 8) * PS_STR + c + 1] = f2tf32(p11);
        }
        s0 += __shfl_xor_sync(0xffffffffu, s0, 1);
        s0 += __shfl_xor_sync(0xffffffffu, s0, 2);
        s1 += __shfl_xor_sync(0xffffffffu, s1, 1);
        s1 += __shfl_xor_sync(0xffffffffu, s1, 2);
        l0 = l0 * al0 + s0;
        l1 = l1 * al1 + s1;

#pragma unroll
        for (int nf = 0; nf < 8; nf++) {
            accO[nf][0] *= al0;
            accO[nf][1] *= al0;
            accO[nf][2] *= al1;
            accO[nf][3] *= al1;
        }
        __syncwarp();   // P rows are warp-private

        // O += P @ V
#pragma unroll
        for (int kb = 0; kb < 8; kb++) {
            uint32_t a[4];
            a[0] = Ps[(mr + g) * PS_STR + kb * 8 + t];
            a[1] = Ps[(mr + g + 8) * PS_STR + kb * 8 + t];
            a[2] = Ps[(mr + g) * PS_STR + kb * 8 + t + 4];
            a[3] = Ps[(mr + g + 8) * PS_STR + kb * 8 + t + 4];
#pragma unroll
            for (int nf = 0; nf < 8; nf++) {
                uint32_t b[2];
                b[0] = Vs[(kb * 8 + t) * VS_STR + nf * 8 + g];
                b[1] = Vs[(kb * 8 + t + 4) * VS_STR + nf * 8 + g];
                mma_tf32(accO[nf], a, b);
            }
        }
    }

    // Epilogue: normalize and write flat ctx layout
    const float inv0 = 1.0f / l0;
    const float inv1 = 1.0f / l1;
    const int bb = bh >> 4, h = bh & 15;
    const int s0r = q0 + mr + g;
#pragma unroll
    for (int nf = 0; nf < 8; nf++) {
        int d = nf * 8 + 2 * t;
        float2 v0 = { accO[nf][0] * inv0, accO[nf][1] * inv0 };
        float2 v1 = { accO[nf][2] * inv1, accO[nf][3] * inv1 };
        *(float2*)(g_ctx + ((size_t)(bb * SS + s0r)) * HID + h * DD + d) = v0;
        *(float2*)(g_ctx + ((size_t)(bb * SS + s0r + 8)) * HID + h * DD + d) = v1;
    }
}

// ----------------------------------------------------------------------------
// Output projection (TF32 MMA, DOUBLE-buffered — proven R6 structure).
// out = ctx @ Wo + bo. M=4096, N=1024, K=1024. grid (8,32).
// ----------------------------------------------------------------------------
__global__ __launch_bounds__(256) void oproj_mma_kernel(
    const float* __restrict__ Wo, const float* __restrict__ bo,
    float* __restrict__ out)
{
    __shared__ uint32_t As[2][128][20];
    __shared__ uint32_t Bs[2][16][136];

    const int m0 = blockIdx.y * 128;
    const int n0 = blockIdx.x * 128;
    const int tid = threadIdx.x;
    const int wid = tid >> 5, lane = tid & 31;
    const int g = lane >> 2, t = lane & 3;
    const int wm = wid >> 1, wn = wid & 1;

    const int arow = tid >> 2,  ac4 = (tid & 3) * 4;
    const int brow = tid >> 5,  bn4 = (tid & 31) * 4;

    float acc[2][8][4];
#pragma unroll
    for (int i = 0; i < 2; i++)
#pragma unroll
        for (int j = 0; j < 8; j++)
#pragma unroll
            for (int r = 0; r < 4; r++) acc[i][j][r] = 0.0f;

    float4 ra[2], rb[2];
#pragma unroll
    for (int u = 0; u < 2; u++) {
        ra[u] = *(const float4*)(g_ctx + (size_t)(m0 + arow + u * 64) * HID + ac4);
        rb[u] = *(const float4*)(Wo + (size_t)(brow + u * 8) * HID + n0 + bn4);
    }
#pragma unroll
    for (int u = 0; u < 2; u++) {
        uint32_t* pa = &As[0][arow + u * 64][ac4];
        pa[0] = f2tf32(ra[u].x); pa[1] = f2tf32(ra[u].y);
        pa[2] = f2tf32(ra[u].z); pa[3] = f2tf32(ra[u].w);
        uint32_t* pb = &Bs[0][brow + u * 8][bn4];
        pb[0] = f2tf32(rb[u].x); pb[1] = f2tf32(rb[u].y);
        pb[2] = f2tf32(rb[u].z); pb[3] = f2tf32(rb[u].w);
    }
    __syncthreads();

    int buf = 0;
    for (int k0 = 0; k0 < HID; k0 += 16) {
        const bool has_next = (k0 + 16 < HID);
        if (has_next) {
#pragma unroll
            for (int u = 0; u < 2; u++) {
                ra[u] = *(const float4*)(g_ctx + (size_t)(m0 + arow + u * 64) * HID + k0 + 16 + ac4);
                rb[u] = *(const float4*)(Wo + (size_t)(k0 + 16 + brow + u * 8) * HID + n0 + bn4);
            }
        }

#pragma unroll
        for (int ks = 0; ks < 2; ks++) {
            const int kb = ks * 8;
            uint32_t a[2][4], b[8][2];
#pragma unroll
            for (int ma = 0; ma < 2; ma++) {
                int row = wm * 32 + ma * 16 + g;
                a[ma][0] = As[buf][row][kb + t];
                a[ma][1] = As[buf][row + 8][kb + t];
                a[ma][2] = As[buf][row][kb + t + 4];
                a[ma][3] = As[buf][row + 8][kb + t + 4];
            }
#pragma unroll
            for (int na = 0; na < 8; na++) {
                int n = wn * 64 + na * 8 + g;
                b[na][0] = Bs[buf][kb + t][n];
                b[na][1] = Bs[buf][kb + t + 4][n];
            }
#pragma unroll
            for (int ma = 0; ma < 2; ma++)
#pragma unroll
                for (int na = 0; na < 8; na++)
                    mma_tf32(acc[ma][na], a[ma], b[na]);
        }

        if (has_next) {
            const int nb = buf ^ 1;
#pragma unroll
            for (int u = 0; u < 2; u++) {
                uint32_t* pa = &As[nb][arow + u * 64][ac4];
                pa[0] = f2tf32(ra[u].x); pa[1] = f2tf32(ra[u].y);
                pa[2] = f2tf32(ra[u].z); pa[3] = f2tf32(ra[u].w);
                uint32_t* pb = &Bs[nb][brow + u * 8][bn4];
                pb[0] = f2tf32(rb[u].x); pb[1] = f2tf32(rb[u].y);
                pb[2] = f2tf32(rb[u].z); pb[3] = f2tf32(rb[u].w);
            }
        }
        __syncthreads();
        buf ^= 1;
    }

#pragma unroll
    for (int ma = 0; ma < 2; ma++) {
#pragma unroll
        for (int na = 0; na < 8; na++) {
            int m = m0 + wm * 32 + ma * 16 + g;
            int n = n0 + wn * 64 + na * 8 + 2 * t;
            float b0 = bo[n], b1 = bo[n + 1];
            float2 v0 = { acc[ma][na][0] + b0, acc[ma][na][1] + b1 };
            float2 v1 = { acc[ma][na][2] + b0, acc[ma][na][3] + b1 };
            *(float2*)(out + (size_t)m * HID + n) = v0;
            *(float2*)(out + (size_t)(m + 8) * HID + n) = v1;
        }
    }
}

// ----------------------------------------------------------------------------
extern "C" void kernel_launch(void* const* d_in, const int* in_sizes, int n_in,
                              void* d_out, int out_size)
{
    const float* X  = (const float*)d_in[0];
    const float* Wq = (const float*)d_in[1];
    const float* bq = (const float*)d_in[2];
    const float* Wk = (const float*)d_in[3];
    const float* bk = (const float*)d_in[4];
    const float* Wv = (const float*)d_in[5];
    const float* bv = (const float*)d_in[6];
    const float* Wo = (const float*)d_in[7];
    const float* bo = (const float*)d_in[8];
    float* out = (float*)d_out;

    // Idempotent, not a stream op — graph-capture safe, no static guards.
    cudaFuncSetAttribute(flash_kernel,
                         cudaFuncAttributeMaxDynamicSharedMemorySize,
                         FLASH_SMEM_BYTES);

    qkv_mma_kernel<<<dim3(HID / 128, MM / 128, 3), 256>>>(X, Wq, bq, Wk, bk, Wv, bv);

    flash_kernel<<<dim3(SS / 128, BH), 256, FLASH_SMEM_BYTES>>>();

    oproj_mma_kernel<<<dim3(HID / 128, MM / 128), 256>>>(Wo, bo, out);
}

// round 13
// speedup vs baseline: 1.5824x; 1.0246x over previous
#include <cuda_runtime.h>
#include <cuda_bf16.h>
#include <math.h>
#include <stdint.h>

// Problem constants
#define BB   2
#define SS   2048
#define HH   16
#define DD   64
#define HID  1024
#define MM   (BB*SS)        // 4096
#define BH   (BB*HH)        // 32

// Scratch (device globals; allocation-guard safe)
__device__ float g_q[BH * SS * DD];   // [bh][s][d]  (tf32-rounded, pre-scaled 1/8)
__device__ float g_k[BH * SS * DD];   // tf32-rounded
__device__ float g_v[BH * SS * DD];   // tf32-rounded
__device__ float g_ctx[MM * HID];     // [b*S+s][h*64+d], tf32-rounded
__device__ float g_x[MM * HID];       // tf32-rounded copy of hidden_states
__device__ float g_w[4][HID * HID];   // tf32-rounded Wq, Wk, Wv, Wo

// omega[l] = 10000^(-l/10)
__device__ __constant__ float OMEGA[10] = {
    1.0f, 0.3981071705534972f, 0.15848931924611134f, 0.0630957344480193f,
    0.025118864315095794f, 0.01f, 0.003981071705534973f, 0.001584893192461114f,
    0.000630957344480193f, 0.00025118864315095795f
};

// ----------------------------------------------------------------------------
// Helpers
// ----------------------------------------------------------------------------
__device__ __forceinline__ uint32_t f2tf32(float x) {
    uint32_t r;
    asm("cvt.rna.tf32.f32 %0, %1;" : "=r"(r) : "f"(x));
    return r;
}

__device__ __forceinline__ void mma_tf32(float* d, const uint32_t* a, const uint32_t* b) {
    asm volatile(
        "mma.sync.aligned.m16n8k8.row.col.f32.tf32.tf32.f32 "
        "{%0,%1,%2,%3}, {%4,%5,%6,%7}, {%8,%9}, {%0,%1,%2,%3};"
        : "+f"(d[0]), "+f"(d[1]), "+f"(d[2]), "+f"(d[3])
        : "r"(a[0]), "r"(a[1]), "r"(a[2]), "r"(a[3]), "r"(b[0]), "r"(b[1]));
}

__device__ __forceinline__ uint32_t smem_u32(const void* p) {
    uint32_t a;
    asm("{ .reg .u64 t; cvta.to.shared.u64 t, %1; cvt.u32.u64 %0, t; }" : "=r"(a) : "l"(p));
    return a;
}

#define CP_ASYNC16(dst, src) \
    asm volatile("cp.async.cg.shared.global [%0], [%1], 16;" :: "r"(dst), "l"(src))
#define CP_COMMIT() asm volatile("cp.async.commit_group;" ::: "memory")
#define CP_WAIT0()  asm volatile("cp.async.wait_group 0;" ::: "memory")

// ----------------------------------------------------------------------------
// Pre-pass: tf32-round X and the 4 weight matrices into device globals.
// 8M floats = 2M float4; grid 8192 x 256.
// ----------------------------------------------------------------------------
__global__ __launch_bounds__(256) void round_kernel(
    const float* __restrict__ X,
    const float* __restrict__ Wq, const float* __restrict__ Wk,
    const float* __restrict__ Wv, const float* __restrict__ Wo)
{
    const size_t XQ = (size_t)MM * HID / 4;       // 1M float4
    const size_t WQ = (size_t)HID * HID / 4;      // 256K float4
    size_t i = (size_t)blockIdx.x * 256 + threadIdx.x;
    const float* src;
    float* dst;
    size_t off;
    if (i < XQ) {
        src = X; dst = g_x; off = i;
    } else {
        size_t j = i - XQ;
        int w = (int)(j / WQ);
        off = j - (size_t)w * WQ;
        src = (w == 0) ? Wq : (w == 1) ? Wk : (w == 2) ? Wv : Wo;
        dst = g_w[w];
    }
    float4 v = ((const float4*)src)[off];
    uint4 o = { f2tf32(v.x), f2tf32(v.y), f2tf32(v.z), f2tf32(v.w) };
    ((uint4*)dst)[off] = o;
}

// ----------------------------------------------------------------------------
// QKV projection (TF32 MMA, cp.async double-buffered staging from pre-rounded
// inputs — no cvt, no register staging): C = g_x @ g_w[z] + b -> [bh][s][d],
// RoPE fused into epilogue for q,k; q additionally pre-scaled by 1/8 and all
// outputs stored tf32-rounded for the downstream flash kernel.
// BM=128, BN=128, BK=16. Warp grid 4x2, warp tile 32x64. grid (8,32,3).
// ----------------------------------------------------------------------------
__global__ __launch_bounds__(256) void qkv_mma_kernel(
    const float* __restrict__ bq, const float* __restrict__ bk,
    const float* __restrict__ bv)
{
    const int z = blockIdx.z;
    const float* __restrict__ W    = g_w[z];
    const float* __restrict__ bias = (z == 0) ? bq : (z == 1) ? bk : bv;
    float* __restrict__ dst        = (z == 0) ? g_q : (z == 1) ? g_k : g_v;

    __shared__ __align__(16) uint32_t As[2][128][20];
    __shared__ __align__(16) uint32_t Bs[2][16][136];

    const int m0 = blockIdx.y * 128;
    const int n0 = blockIdx.x * 128;
    const int tid = threadIdx.x;
    const int wid = tid >> 5, lane = tid & 31;
    const int g = lane >> 2, t = lane & 3;
    const int wm = wid >> 1, wn = wid & 1;

    const uint32_t aAs = smem_u32(As);
    const uint32_t aBs = smem_u32(Bs);
    const int arow = tid >> 2, ac4 = (tid & 3) * 4;  // + 64*it rows
    const int bkk = tid >> 5,  bn4 = (tid & 31) * 4; // + 8*it k-rows

    float acc[2][8][4];
#pragma unroll
    for (int i = 0; i < 2; i++)
#pragma unroll
        for (int j = 0; j < 8; j++)
#pragma unroll
            for (int r = 0; r < 4; r++) acc[i][j][r] = 0.0f;

    // stage buf <- k0 chunk (4 cp.asyncs per thread)
    auto stage = [&](int buf, int k0) {
#pragma unroll
        for (int it = 0; it < 2; it++) {
            int r = arow + it * 64;
            CP_ASYNC16(aAs + (uint32_t)((buf * 128 + r) * 20 + ac4) * 4,
                       g_x + (size_t)(m0 + r) * HID + k0 + ac4);
            int kk = bkk + it * 8;
            CP_ASYNC16(aBs + (uint32_t)((buf * 16 + kk) * 136 + bn4) * 4,
                       W + (size_t)(k0 + kk) * HID + n0 + bn4);
        }
    };

    stage(0, 0);
    CP_COMMIT();
    CP_WAIT0();
    __syncthreads();

    int buf = 0;
    for (int k0 = 0; k0 < HID; k0 += 16) {
        const bool has_next = (k0 + 16 < HID);
        if (has_next) { stage(buf ^ 1, k0 + 16); CP_COMMIT(); }

#pragma unroll
        for (int ks = 0; ks < 2; ks++) {
            const int kb = ks * 8;
            uint32_t a[2][4], b[8][2];
#pragma unroll
            for (int ma = 0; ma < 2; ma++) {
                int row = wm * 32 + ma * 16 + g;
                a[ma][0] = As[buf][row][kb + t];
                a[ma][1] = As[buf][row + 8][kb + t];
                a[ma][2] = As[buf][row][kb + t + 4];
                a[ma][3] = As[buf][row + 8][kb + t + 4];
            }
#pragma unroll
            for (int na = 0; na < 8; na++) {
                int n = wn * 64 + na * 8 + g;
                b[na][0] = Bs[buf][kb + t][n];
                b[na][1] = Bs[buf][kb + t + 4][n];
            }
#pragma unroll
            for (int ma = 0; ma < 2; ma++)
#pragma unroll
                for (int na = 0; na < 8; na++)
                    mma_tf32(acc[ma][na], a[ma], b[na]);
        }

        if (has_next) CP_WAIT0();
        __syncthreads();
        buf ^= 1;
    }

    // Epilogue: +bias, fused axial RoPE (q,k), pre-scale q by 1/8, store
    // tf32-rounded (downstream flash consumes raw bits).
    const bool do_rope = (z < 2);
    const float osc = (z == 0) ? 0.125f : 1.0f;
#pragma unroll
    for (int ma = 0; ma < 2; ma++) {
#pragma unroll
        for (int na = 0; na < 8; na++) {
            int m = m0 + wm * 32 + ma * 16 + g;
            int n = n0 + wn * 64 + na * 8 + 2 * t;
            float b0 = bias[n], b1 = bias[n + 1];
            int h = n >> 6, d = n & 63;

            float y00 = acc[ma][na][0] + b0;
            float y01 = acc[ma][na][1] + b1;
            float y10 = acc[ma][na][2] + b0;
            float y11 = acc[ma][na][3] + b1;

            if (do_rope && d < 60) {
                int seg = d / 20;
                int j = d - seg * 20;
                int l0 = (j < 10) ? j : j - 10;
                int l1 = (j + 1 < 10) ? j + 1 : j - 9;
                float om0 = OMEGA[l0], om1 = OMEGA[l1];
                {
                    int s = m & 2047;
                    int pos = (seg == 0) ? (s >> 8) : (seg == 1) ? ((s >> 4) & 15) : (s & 15);
                    float p = (float)pos;
                    float sn0, cs0, sn1, cs1;
                    sincosf(p * om0, &sn0, &cs0);
                    sincosf(p * om1, &sn1, &cs1);
                    float r0 = y00 * cs0 - y01 * sn0;
                    float r1 = y01 * cs1 + y00 * sn1;
                    y00 = r0; y01 = r1;
                }
                {
                    int s = (m + 8) & 2047;
                    int pos = (seg == 0) ? (s >> 8) : (seg == 1) ? ((s >> 4) & 15) : (s & 15);
                    float p = (float)pos;
                    float sn0, cs0, sn1, cs1;
                    sincosf(p * om0, &sn0, &cs0);
                    sincosf(p * om1, &sn1, &cs1);
                    float r0 = y10 * cs0 - y11 * sn0;
                    float r1 = y11 * cs1 + y10 * sn1;
                    y10 = r0; y11 = r1;
                }
            }
            {
                int b = m >> 11, s = m & 2047;
                float2 v = { __uint_as_float(f2tf32(osc * y00)),
                             __uint_as_float(f2tf32(osc * y01)) };
                *(float2*)(dst + (((size_t)((b << 4) + h)) * SS + s) * DD + d) = v;
            }
            {
                int m2 = m + 8;
                int b = m2 >> 11, s = m2 & 2047;
                float2 v = { __uint_as_float(f2tf32(osc * y10)),
                             __uint_as_float(f2tf32(osc * y11)) };
                *(float2*)(dst + (((size_t)((b << 4) + h)) * SS + s) * DD + d) = v;
            }
        }
    }
}

// ----------------------------------------------------------------------------
// Fused flash attention: inputs are pre-rounded (and q pre-scaled), so staging
// is pure bit-copies (st.shared.v4, no cvt). Single smem buffer (105 KB ->
// 2 CTAs/SM) + register prefetch of K/V (proven R11 structure).
// grid: (SS/128, BH), 256 threads.
// ----------------------------------------------------------------------------
#define QS_STR 68
#define KS_STR 68
#define VS_STR 72
#define PS_STR 68
#define SM_Q 0
#define SM_K (SM_Q + 128 * QS_STR)
#define SM_V (SM_K + 64 * KS_STR)
#define SM_P (SM_V + 64 * VS_STR)
#define FLASH_SMEM_WORDS (SM_P + 128 * PS_STR)
#define FLASH_SMEM_BYTES (FLASH_SMEM_WORDS * 4)

__global__ __launch_bounds__(256, 2) void flash_kernel()
{
    extern __shared__ uint32_t sm[];
    uint32_t* __restrict__ Qs = sm + SM_Q;
    uint32_t* __restrict__ Ks = sm + SM_K;
    uint32_t* __restrict__ Vs = sm + SM_V;
    uint32_t* __restrict__ Ps = sm + SM_P;

    const int bh = blockIdx.y;
    const int q0 = blockIdx.x * 128;
    const float* __restrict__ Q = g_q + (size_t)bh * SS * DD;
    const float* __restrict__ K = g_k + (size_t)bh * SS * DD;
    const float* __restrict__ V = g_v + (size_t)bh * SS * DD;

    const int tid = threadIdx.x;
    const int wid = tid >> 5, lane = tid & 31;
    const int g = lane >> 2, t = lane & 3;
    const int mr = wid * 16;

    const int srow = tid >> 4, sc4 = (tid & 15) * 4;

    // Q tile (pre-rounded, pre-scaled): raw copy
#pragma unroll
    for (int i = tid; i < 128 * 16; i += 256) {
        int row = i >> 4, c4 = (i & 15) * 4;
        float4 v = *(const float4*)(Q + (size_t)(q0 + row) * DD + c4);
        *(float4*)&Qs[row * QS_STR + c4] = v;
    }

    // Prefetch K/V tile 0 into registers
    float4 rk[4], rv[4];
#pragma unroll
    for (int u = 0; u < 4; u++) {
        rk[u] = *(const float4*)(K + (size_t)(srow + u * 16) * DD + sc4);
        rv[u] = *(const float4*)(V + (size_t)(srow + u * 16) * DD + sc4);
    }

    float accO[8][4];
#pragma unroll
    for (int j = 0; j < 8; j++)
#pragma unroll
        for (int r = 0; r < 4; r++) accO[j][r] = 0.0f;
    float m0 = -1e30f, m1 = -1e30f, l0 = 0.0f, l1 = 0.0f;

    for (int kt = 0; kt < SS; kt += 64) {
        __syncthreads();
        // Commit prefetched registers to smem (raw v4 stores, no cvt)
#pragma unroll
        for (int u = 0; u < 4; u++) {
            *(float4*)&Ks[(srow + u * 16) * KS_STR + sc4] = rk[u];
            *(float4*)&Vs[(srow + u * 16) * VS_STR + sc4] = rv[u];
        }
        __syncthreads();

        const bool has_next = (kt + 64 < SS);
        if (has_next) {
#pragma unroll
            for (int u = 0; u < 4; u++) {
                rk[u] = *(const float4*)(K + (size_t)(kt + 64 + srow + u * 16) * DD + sc4);
                rv[u] = *(const float4*)(V + (size_t)(kt + 64 + srow + u * 16) * DD + sc4);
            }
        }

        // S = (Q/8) K^T  (warp tile 16 x 64)
        float accS[8][4];
#pragma unroll
        for (int j = 0; j < 8; j++)
#pragma unroll
            for (int r = 0; r < 4; r++) accS[j][r] = 0.0f;

#pragma unroll
        for (int kb = 0; kb < 8; kb++) {
            uint32_t a[4];
            a[0] = Qs[(mr + g) * QS_STR + kb * 8 + t];
            a[1] = Qs[(mr + g + 8) * QS_STR + kb * 8 + t];
            a[2] = Qs[(mr + g) * QS_STR + kb * 8 + t + 4];
            a[3] = Qs[(mr + g + 8) * QS_STR + kb * 8 + t + 4];
#pragma unroll
            for (int nf = 0; nf < 8; nf++) {
                uint32_t b[2];
                b[0] = Ks[(nf * 8 + g) * KS_STR + kb * 8 + t];
                b[1] = Ks[(nf * 8 + g) * KS_STR + kb * 8 + t + 4];
                mma_tf32(accS[nf], a, b);
            }
        }

        // Online softmax (rows mr+g and mr+g+8; 4-lane quad shares a row)
        float r0 = -1e30f, r1 = -1e30f;
#pragma unroll
        for (int nf = 0; nf < 8; nf++) {
            r0 = fmaxf(r0, fmaxf(accS[nf][0], accS[nf][1]));
            r1 = fmaxf(r1, fmaxf(accS[nf][2], accS[nf][3]));
        }
        r0 = fmaxf(r0, __shfl_xor_sync(0xffffffffu, r0, 1));
        r0 = fmaxf(r0, __shfl_xor_sync(0xffffffffu, r0, 2));
        r1 = fmaxf(r1, __shfl_xor_sync(0xffffffffu, r1, 1));
        r1 = fmaxf(r1, __shfl_xor_sync(0xffffffffu, r1, 2));

        float mn0 = fmaxf(m0, r0);
        float mn1 = fmaxf(m1, r1);
        float al0 = __expf(m0 - mn0);
        float al1 = __expf(m1 - mn1);
        m0 = mn0; m1 = mn1;

        float s0 = 0.0f, s1 = 0.0f;
#pragma unroll
        for (int nf = 0; nf < 8; nf++) {
            float p00 = __expf(accS[nf][0] - m0);
            float p01 = __expf(accS[nf][1] - m0);
            float p10 = __expf(accS[nf][2] - m1);
            float p11 = __expf(accS[nf][3] - m1);
            s0 += p00 + p01;
            s1 += p10 + p11;
            int c = nf * 8 + 2 * t;
            Ps[(mr + g) * PS_STR + c]         = f2tf32(p00);
            Ps[(mr + g) * PS_STR + c + 1]     = f2tf32(p01);
            Ps[(mr + g + 8) * PS_STR + c]     = f2tf32(p10);
            Ps[(mr + g + 8) * PS_STR + c + 1] = f2tf32(p11);
        }
        s0 += __shfl_xor_sync(0xffffffffu, s0, 1);
        s0 += __shfl_xor_sync(0xffffffffu, s0, 2);
        s1 += __shfl_xor_sync(0xffffffffu, s1, 1);
        s1 += __shfl_xor_sync(0xffffffffu, s1, 2);
        l0 = l0 * al0 + s0;
        l1 = l1 * al1 + s1;

#pragma unroll
        for (int nf = 0; nf < 8; nf++) {
            accO[nf][0] *= al0;
            accO[nf][1] *= al0;
            accO[nf][2] *= al1;
            accO[nf][3] *= al1;
        }
        __syncwarp();   // P rows are warp-private

        // O += P @ V
#pragma unroll
        for (int kb = 0; kb < 8; kb++) {
            uint32_t a[4];
            a[0] = Ps[(mr + g) * PS_STR + kb * 8 + t];
            a[1] = Ps[(mr + g + 8) * PS_STR + kb * 8 + t];
            a[2] = Ps[(mr + g) * PS_STR + kb * 8 + t + 4];
            a[3] = Ps[(mr + g + 8) * PS_STR + kb * 8 + t + 4];
#pragma unroll
            for (int nf = 0; nf < 8; nf++) {
                uint32_t b[2];
                b[0] = Vs[(kb * 8 + t) * VS_STR + nf * 8 + g];
                b[1] = Vs[(kb * 8 + t + 4) * VS_STR + nf * 8 + g];
                mma_tf32(accO[nf], a, b);
            }
        }
    }

    // Epilogue: normalize, store tf32-rounded (oproj consumes raw bits)
    const float inv0 = 1.0f / l0;
    const float inv1 = 1.0f / l1;
    const int bb = bh >> 4, h = bh & 15;
    const int s0r = q0 + mr + g;
#pragma unroll
    for (int nf = 0; nf < 8; nf++) {
        int d = nf * 8 + 2 * t;
        float2 v0 = { __uint_as_float(f2tf32(accO[nf][0] * inv0)),
                      __uint_as_float(f2tf32(accO[nf][1] * inv0)) };
        float2 v1 = { __uint_as_float(f2tf32(accO[nf][2] * inv1)),
                      __uint_as_float(f2tf32(accO[nf][3] * inv1)) };
        *(float2*)(g_ctx + ((size_t)(bb * SS + s0r)) * HID + h * DD + d) = v0;
        *(float2*)(g_ctx + ((size_t)(bb * SS + s0r + 8)) * HID + h * DD + d) = v1;
    }
}

// ----------------------------------------------------------------------------
// Output projection (TF32 MMA, cp.async double-buffered staging; inputs
// pre-rounded): out = g_ctx @ g_w[3] + bo. grid (8,32).
// ----------------------------------------------------------------------------
__global__ __launch_bounds__(256) void oproj_mma_kernel(
    const float* __restrict__ bo, float* __restrict__ out)
{
    const float* __restrict__ W = g_w[3];

    __shared__ __align__(16) uint32_t As[2][128][20];
    __shared__ __align__(16) uint32_t Bs[2][16][136];

    const int m0 = blockIdx.y * 128;
    const int n0 = blockIdx.x * 128;
    const int tid = threadIdx.x;
    const int wid = tid >> 5, lane = tid & 31;
    const int g = lane >> 2, t = lane & 3;
    const int wm = wid >> 1, wn = wid & 1;

    const uint32_t aAs = smem_u32(As);
    const uint32_t aBs = smem_u32(Bs);
    const int arow = tid >> 2, ac4 = (tid & 3) * 4;
    const int bkk = tid >> 5,  bn4 = (tid & 31) * 4;

    float acc[2][8][4];
#pragma unroll
    for (int i = 0; i < 2; i++)
#pragma unroll
        for (int j = 0; j < 8; j++)
#pragma unroll
            for (int r = 0; r < 4; r++) acc[i][j][r] = 0.0f;

    auto stage = [&](int buf, int k0) {
#pragma unroll
        for (int it = 0; it < 2; it++) {
            int r = arow + it * 64;
            CP_ASYNC16(aAs + (uint32_t)((buf * 128 + r) * 20 + ac4) * 4,
                       g_ctx + (size_t)(m0 + r) * HID + k0 + ac4);
            int kk = bkk + it * 8;
            CP_ASYNC16(aBs + (uint32_t)((buf * 16 + kk) * 136 + bn4) * 4,
                       W + (size_t)(k0 + kk) * HID + n0 + bn4);
        }
    };

    stage(0, 0);
    CP_COMMIT();
    CP_WAIT0();
    __syncthreads();

    int buf = 0;
    for (int k0 = 0; k0 < HID; k0 += 16) {
        const bool has_next = (k0 + 16 < HID);
        if (has_next) { stage(buf ^ 1, k0 + 16); CP_COMMIT(); }

#pragma unroll
        for (int ks = 0; ks < 2; ks++) {
            const int kb = ks * 8;
            uint32_t a[2][4], b[8][2];
#pragma unroll
            for (int ma = 0; ma < 2; ma++) {
                int row = wm * 32 + ma * 16 + g;
                a[ma][0] = As[buf][row][kb + t];
                a[ma][1] = As[buf][row + 8][kb + t];
                a[ma][2] = As[buf][row][kb + t + 4];
                a[ma][3] = As[buf][row + 8][kb + t + 4];
            }
#pragma unroll
            for (int na = 0; na < 8; na++) {
                int n = wn * 64 + na * 8 + g;
                b[na][0] = Bs[buf][kb + t][n];
                b[na][1] = Bs[buf][kb + t + 4][n];
            }
#pragma unroll
            for (int ma = 0; ma < 2; ma++)
#pragma unroll
                for (int na = 0; na < 8; na++)
                    mma_tf32(acc[ma][na], a[ma], b[na]);
        }

        if (has_next) CP_WAIT0();
        __syncthreads();
        buf ^= 1;
    }

#pragma unroll
    for (int ma = 0; ma < 2; ma++) {
#pragma unroll
        for (int na = 0; na < 8; na++) {
            int m = m0 + wm * 32 + ma * 16 + g;
            int n = n0 + wn * 64 + na * 8 + 2 * t;
            float b0 = bo[n], b1 = bo[n + 1];
            float2 v0 = { acc[ma][na][0] + b0, acc[ma][na][1] + b1 };
            float2 v1 = { acc[ma][na][2] + b0, acc[ma][na][3] + b1 };
            *(float2*)(out + (size_t)m * HID + n) = v0;
            *(float2*)(out + (size_t)(m + 8) * HID + n) = v1;
        }
    }
}

// ----------------------------------------------------------------------------
extern "C" void kernel_launch(void* const* d_in, const int* in_sizes, int n_in,
                              void* d_out, int out_size)
{
    const float* X  = (const float*)d_in[0];
    const float* Wq = (const float*)d_in[1];
    const float* bq = (const float*)d_in[2];
    const float* Wk = (const float*)d_in[3];
    const float* bk = (const float*)d_in[4];
    const float* Wv = (const float*)d_in[5];
    const float* bv = (const float*)d_in[6];
    const float* Wo = (const float*)d_in[7];
    const float* bo = (const float*)d_in[8];
    float* out = (float*)d_out;

    // Idempotent, not a stream op — graph-capture safe, no static guards.
    cudaFuncSetAttribute(flash_kernel,
                         cudaFuncAttributeMaxDynamicSharedMemorySize,
                         FLASH_SMEM_BYTES);

    // Pre-round X and weights to tf32 once (8M floats = 2M float4).
    round_kernel<<<8192, 256>>>(X, Wq, Wk, Wv, Wo);

    qkv_mma_kernel<<<dim3(HID / 128, MM / 128, 3), 256>>>(bq, bk, bv);

    flash_kernel<<<dim3(SS / 128, BH), 256, FLASH_SMEM_BYTES>>>();

    oproj_mma_kernel<<<dim3(HID / 128, MM / 128), 256>>>(bo, out);
}

// round 14
// speedup vs baseline: 1.6994x; 1.0739x over previous
#include <cuda_runtime.h>
#include <cuda_bf16.h>
#include <math.h>
#include <stdint.h>

// Problem constants
#define BB   2
#define SS   2048
#define HH   16
#define DD   64
#define HID  1024
#define MM   (BB*SS)        // 4096
#define BH   (BB*HH)        // 32

// Scratch (device globals; allocation-guard safe)
__device__ float g_q[BH * SS * DD];   // [bh][s][d]  (tf32-rounded, pre-scaled 1/8)
__device__ float g_k[BH * SS * DD];   // tf32-rounded
__device__ float g_v[BH * SS * DD];   // tf32-rounded
__device__ float g_ctx[MM * HID];     // [b*S+s][h*64+d], tf32-rounded
__device__ float g_x[MM * HID];       // tf32-rounded copy of hidden_states
__device__ float g_w[4][HID * HID];   // tf32-rounded Wq, Wk, Wv, Wo

// omega[l] = 10000^(-l/10)
__device__ __constant__ float OMEGA[10] = {
    1.0f, 0.3981071705534972f, 0.15848931924611134f, 0.0630957344480193f,
    0.025118864315095794f, 0.01f, 0.003981071705534973f, 0.001584893192461114f,
    0.000630957344480193f, 0.00025118864315095795f
};

// ----------------------------------------------------------------------------
// Helpers
// ----------------------------------------------------------------------------
__device__ __forceinline__ uint32_t f2tf32(float x) {
    uint32_t r;
    asm("cvt.rna.tf32.f32 %0, %1;" : "=r"(r) : "f"(x));
    return r;
}

__device__ __forceinline__ void mma_tf32(float* d, const uint32_t* a, const uint32_t* b) {
    asm volatile(
        "mma.sync.aligned.m16n8k8.row.col.f32.tf32.tf32.f32 "
        "{%0,%1,%2,%3}, {%4,%5,%6,%7}, {%8,%9}, {%0,%1,%2,%3};"
        : "+f"(d[0]), "+f"(d[1]), "+f"(d[2]), "+f"(d[3])
        : "r"(a[0]), "r"(a[1]), "r"(a[2]), "r"(a[3]), "r"(b[0]), "r"(b[1]));
}

__device__ __forceinline__ uint32_t smem_u32(const void* p) {
    uint32_t a;
    asm("{ .reg .u64 t; cvta.to.shared.u64 t, %1; cvt.u32.u64 %0, t; }" : "=r"(a) : "l"(p));
    return a;
}

#define CP_ASYNC16(dst, src) \
    asm volatile("cp.async.cg.shared.global [%0], [%1], 16;" :: "r"(dst), "l"(src))
#define CP_COMMIT() asm volatile("cp.async.commit_group;" ::: "memory")
#define CP_WAIT0()  asm volatile("cp.async.wait_group 0;" ::: "memory")

// ----------------------------------------------------------------------------
// Pre-pass: tf32-round X and the 4 weight matrices into device globals.
// ----------------------------------------------------------------------------
__global__ __launch_bounds__(256) void round_kernel(
    const float* __restrict__ X,
    const float* __restrict__ Wq, const float* __restrict__ Wk,
    const float* __restrict__ Wv, const float* __restrict__ Wo)
{
    const size_t XQ = (size_t)MM * HID / 4;       // 1M float4
    const size_t WQ = (size_t)HID * HID / 4;      // 256K float4
    size_t i = (size_t)blockIdx.x * 256 + threadIdx.x;
    const float* src;
    float* dst;
    size_t off;
    if (i < XQ) {
        src = X; dst = g_x; off = i;
    } else {
        size_t j = i - XQ;
        int w = (int)(j / WQ);
        off = j - (size_t)w * WQ;
        src = (w == 0) ? Wq : (w == 1) ? Wk : (w == 2) ? Wv : Wo;
        dst = g_w[w];
    }
    float4 v = ((const float4*)src)[off];
    uint4 o = { f2tf32(v.x), f2tf32(v.y), f2tf32(v.z), f2tf32(v.w) };
    ((uint4*)dst)[off] = o;
}

// ============================================================================
// GEMM (TF32 MMA, BK=32, cp.async double-buffered, dynamic smem 71.7 KB).
// A: [2][128][36] (k + 4 pad), B: [2][32][136]. 32 iterations, 32 MMAs and
// one barrier pair per iteration (vs 16 MMAs at BK=16 previously).
// ============================================================================
#define AST 36
#define BST 136
#define A_WORDS (2 * 128 * AST)       // 9216
#define B_WORDS (2 * 32 * BST)        // 8704
#define GEMM_SMEM_BYTES ((A_WORDS + B_WORDS) * 4)   // 71680

struct GemmCore {
    uint32_t* As;        // smem word ptr
    uint32_t* Bs;
    uint32_t aAs, aBs;   // smem byte addr
    int tid, wid, lane, g, t, wm, wn;
    int arow, aq4;       // A staging: row(+32*it), col 4*aq4
    int bkk, bn4;        // B staging: k-row(+8*it), col bn4

    __device__ __forceinline__ void init(uint32_t* sm) {
        As = sm; Bs = sm + A_WORDS;
        aAs = smem_u32(As); aBs = smem_u32(Bs);
        tid = threadIdx.x;
        wid = tid >> 5; lane = tid & 31;
        g = lane >> 2; t = lane & 3;
        wm = wid >> 1; wn = wid & 1;
        arow = tid >> 3; aq4 = (tid & 7) * 4;     // 32 rows per it, 8 f4/row
        bkk = tid >> 5;  bn4 = (tid & 31) * 4;    // 8 k-rows per it
    }

    __device__ __forceinline__ void stage(const float* __restrict__ A,
                                          const float* __restrict__ W,
                                          int m0, int n0, int buf, int k0) {
#pragma unroll
        for (int it = 0; it < 4; it++) {
            int r = arow + it * 32;
            CP_ASYNC16(aAs + (uint32_t)((buf * 128 + r) * AST + aq4) * 4,
                       A + (size_t)(m0 + r) * HID + k0 + aq4);
            int kk = bkk + it * 8;
            CP_ASYNC16(aBs + (uint32_t)((buf * 32 + kk) * BST + bn4) * 4,
                       W + (size_t)(k0 + kk) * HID + n0 + bn4);
        }
    }

    __device__ __forceinline__ void mainloop(const float* __restrict__ A,
                                             const float* __restrict__ W,
                                             int m0, int n0,
                                             float acc[2][8][4]) {
        stage(A, W, m0, n0, 0, 0);
        CP_COMMIT();
        CP_WAIT0();
        __syncthreads();

        int buf = 0;
        for (int k0 = 0; k0 < HID; k0 += 32) {
            const bool has_next = (k0 + 32 < HID);
            if (has_next) { stage(A, W, m0, n0, buf ^ 1, k0 + 32); CP_COMMIT(); }

#pragma unroll
            for (int ks = 0; ks < 4; ks++) {
                const int kb = ks * 8;
                uint32_t a[2][4], b[8][2];
#pragma unroll
                for (int ma = 0; ma < 2; ma++) {
                    int row = (buf * 128 + wm * 32 + ma * 16 + g) * AST;
                    a[ma][0] = As[row + kb + t];
                    a[ma][1] = As[row + 8 * AST + kb + t];
                    a[ma][2] = As[row + kb + t + 4];
                    a[ma][3] = As[row + 8 * AST + kb + t + 4];
                }
#pragma unroll
                for (int na = 0; na < 8; na++) {
                    int n = wn * 64 + na * 8 + g;
                    b[na][0] = Bs[(buf * 32 + kb + t) * BST + n];
                    b[na][1] = Bs[(buf * 32 + kb + t + 4) * BST + n];
                }
#pragma unroll
                for (int ma = 0; ma < 2; ma++)
#pragma unroll
                    for (int na = 0; na < 8; na++)
                        mma_tf32(acc[ma][na], a[ma], b[na]);
            }

            if (has_next) CP_WAIT0();
            __syncthreads();
            buf ^= 1;
        }
    }
};

// ----------------------------------------------------------------------------
// QKV projection: C = g_x @ g_w[z] + b -> [bh][s][d], RoPE fused (q,k),
// q pre-scaled by 1/8, outputs stored tf32-rounded. grid (8,32,3).
// ----------------------------------------------------------------------------
__global__ __launch_bounds__(256) void qkv_mma_kernel(
    const float* __restrict__ bq, const float* __restrict__ bk,
    const float* __restrict__ bv)
{
    extern __shared__ uint32_t smg[];
    const int z = blockIdx.z;
    const float* __restrict__ W    = g_w[z];
    const float* __restrict__ bias = (z == 0) ? bq : (z == 1) ? bk : bv;
    float* __restrict__ dst        = (z == 0) ? g_q : (z == 1) ? g_k : g_v;

    const int m0 = blockIdx.y * 128;
    const int n0 = blockIdx.x * 128;

    GemmCore core;
    core.init(smg);

    float acc[2][8][4];
#pragma unroll
    for (int i = 0; i < 2; i++)
#pragma unroll
        for (int j = 0; j < 8; j++)
#pragma unroll
            for (int r = 0; r < 4; r++) acc[i][j][r] = 0.0f;

    core.mainloop(g_x, W, m0, n0, acc);

    const int g = core.g, t = core.t, wm = core.wm, wn = core.wn;
    const bool do_rope = (z < 2);
    const float osc = (z == 0) ? 0.125f : 1.0f;
#pragma unroll
    for (int ma = 0; ma < 2; ma++) {
#pragma unroll
        for (int na = 0; na < 8; na++) {
            int m = m0 + wm * 32 + ma * 16 + g;
            int n = n0 + wn * 64 + na * 8 + 2 * t;
            float b0 = bias[n], b1 = bias[n + 1];
            int h = n >> 6, d = n & 63;

            float y00 = acc[ma][na][0] + b0;
            float y01 = acc[ma][na][1] + b1;
            float y10 = acc[ma][na][2] + b0;
            float y11 = acc[ma][na][3] + b1;

            if (do_rope && d < 60) {
                int seg = d / 20;
                int j = d - seg * 20;
                int l0 = (j < 10) ? j : j - 10;
                int l1 = (j + 1 < 10) ? j + 1 : j - 9;
                float om0 = OMEGA[l0], om1 = OMEGA[l1];
                {
                    int s = m & 2047;
                    int pos = (seg == 0) ? (s >> 8) : (seg == 1) ? ((s >> 4) & 15) : (s & 15);
                    float p = (float)pos;
                    float sn0, cs0, sn1, cs1;
                    sincosf(p * om0, &sn0, &cs0);
                    sincosf(p * om1, &sn1, &cs1);
                    float r0 = y00 * cs0 - y01 * sn0;
                    float r1 = y01 * cs1 + y00 * sn1;
                    y00 = r0; y01 = r1;
                }
                {
                    int s = (m + 8) & 2047;
                    int pos = (seg == 0) ? (s >> 8) : (seg == 1) ? ((s >> 4) & 15) : (s & 15);
                    float p = (float)pos;
                    float sn0, cs0, sn1, cs1;
                    sincosf(p * om0, &sn0, &cs0);
                    sincosf(p * om1, &sn1, &cs1);
                    float r0 = y10 * cs0 - y11 * sn0;
                    float r1 = y11 * cs1 + y10 * sn1;
                    y10 = r0; y11 = r1;
                }
            }
            {
                int b = m >> 11, s = m & 2047;
                float2 v = { __uint_as_float(f2tf32(osc * y00)),
                             __uint_as_float(f2tf32(osc * y01)) };
                *(float2*)(dst + (((size_t)((b << 4) + h)) * SS + s) * DD + d) = v;
            }
            {
                int m2 = m + 8;
                int b = m2 >> 11, s = m2 & 2047;
                float2 v = { __uint_as_float(f2tf32(osc * y10)),
                             __uint_as_float(f2tf32(osc * y11)) };
                *(float2*)(dst + (((size_t)((b << 4) + h)) * SS + s) * DD + d) = v;
            }
        }
    }
}

// ----------------------------------------------------------------------------
// Output projection: out = g_ctx @ g_w[3] + bo. grid (8,32).
// ----------------------------------------------------------------------------
__global__ __launch_bounds__(256) void oproj_mma_kernel(
    const float* __restrict__ bo, float* __restrict__ out)
{
    extern __shared__ uint32_t smg[];
    const int m0 = blockIdx.y * 128;
    const int n0 = blockIdx.x * 128;

    GemmCore core;
    core.init(smg);

    float acc[2][8][4];
#pragma unroll
    for (int i = 0; i < 2; i++)
#pragma unroll
        for (int j = 0; j < 8; j++)
#pragma unroll
            for (int r = 0; r < 4; r++) acc[i][j][r] = 0.0f;

    core.mainloop(g_ctx, g_w[3], m0, n0, acc);

    const int g = core.g, t = core.t, wm = core.wm, wn = core.wn;
#pragma unroll
    for (int ma = 0; ma < 2; ma++) {
#pragma unroll
        for (int na = 0; na < 8; na++) {
            int m = m0 + wm * 32 + ma * 16 + g;
            int n = n0 + wn * 64 + na * 8 + 2 * t;
            float b0 = bo[n], b1 = bo[n + 1];
            float2 v0 = { acc[ma][na][0] + b0, acc[ma][na][1] + b1 };
            float2 v1 = { acc[ma][na][2] + b0, acc[ma][na][3] + b1 };
            *(float2*)(out + (size_t)m * HID + n) = v0;
            *(float2*)(out + (size_t)(m + 8) * HID + n) = v1;
        }
    }
}

// ----------------------------------------------------------------------------
// Fused flash attention (unchanged R13 structure: pre-rounded inputs, raw
// bit-copy staging, single smem buffer 105 KB -> 2 CTAs/SM, reg prefetch).
// ----------------------------------------------------------------------------
#define QS_STR 68
#define KS_STR 68
#define VS_STR 72
#define PS_STR 68
#define SM_Q 0
#define SM_K (SM_Q + 128 * QS_STR)
#define SM_V (SM_K + 64 * KS_STR)
#define SM_P (SM_V + 64 * VS_STR)
#define FLASH_SMEM_WORDS (SM_P + 128 * PS_STR)
#define FLASH_SMEM_BYTES (FLASH_SMEM_WORDS * 4)

__global__ __launch_bounds__(256, 2) void flash_kernel()
{
    extern __shared__ uint32_t sm[];
    uint32_t* __restrict__ Qs = sm + SM_Q;
    uint32_t* __restrict__ Ks = sm + SM_K;
    uint32_t* __restrict__ Vs = sm + SM_V;
    uint32_t* __restrict__ Ps = sm + SM_P;

    const int bh = blockIdx.y;
    const int q0 = blockIdx.x * 128;
    const float* __restrict__ Q = g_q + (size_t)bh * SS * DD;
    const float* __restrict__ K = g_k + (size_t)bh * SS * DD;
    const float* __restrict__ V = g_v + (size_t)bh * SS * DD;

    const int tid = threadIdx.x;
    const int wid = tid >> 5, lane = tid & 31;
    const int g = lane >> 2, t = lane & 3;
    const int mr = wid * 16;

    const int srow = tid >> 4, sc4 = (tid & 15) * 4;

#pragma unroll
    for (int i = tid; i < 128 * 16; i += 256) {
        int row = i >> 4, c4 = (i & 15) * 4;
        float4 v = *(const float4*)(Q + (size_t)(q0 + row) * DD + c4);
        *(float4*)&Qs[row * QS_STR + c4] = v;
    }

    float4 rk[4], rv[4];
#pragma unroll
    for (int u = 0; u < 4; u++) {
        rk[u] = *(const float4*)(K + (size_t)(srow + u * 16) * DD + sc4);
        rv[u] = *(const float4*)(V + (size_t)(srow + u * 16) * DD + sc4);
    }

    float accO[8][4];
#pragma unroll
    for (int j = 0; j < 8; j++)
#pragma unroll
        for (int r = 0; r < 4; r++) accO[j][r] = 0.0f;
    float m0 = -1e30f, m1 = -1e30f, l0 = 0.0f, l1 = 0.0f;

    for (int kt = 0; kt < SS; kt += 64) {
        __syncthreads();
#pragma unroll
        for (int u = 0; u < 4; u++) {
            *(float4*)&Ks[(srow + u * 16) * KS_STR + sc4] = rk[u];
            *(float4*)&Vs[(srow + u * 16) * VS_STR + sc4] = rv[u];
        }
        __syncthreads();

        const bool has_next = (kt + 64 < SS);
        if (has_next) {
#pragma unroll
            for (int u = 0; u < 4; u++) {
                rk[u] = *(const float4*)(K + (size_t)(kt + 64 + srow + u * 16) * DD + sc4);
                rv[u] = *(const float4*)(V + (size_t)(kt + 64 + srow + u * 16) * DD + sc4);
            }
        }

        float accS[8][4];
#pragma unroll
        for (int j = 0; j < 8; j++)
#pragma unroll
            for (int r = 0; r < 4; r++) accS[j][r] = 0.0f;

#pragma unroll
        for (int kb = 0; kb < 8; kb++) {
            uint32_t a[4];
            a[0] = Qs[(mr + g) * QS_STR + kb * 8 + t];
            a[1] = Qs[(mr + g + 8) * QS_STR + kb * 8 + t];
            a[2] = Qs[(mr + g) * QS_STR + kb * 8 + t + 4];
            a[3] = Qs[(mr + g + 8) * QS_STR + kb * 8 + t + 4];
#pragma unroll
            for (int nf = 0; nf < 8; nf++) {
                uint32_t b[2];
                b[0] = Ks[(nf * 8 + g) * KS_STR + kb * 8 + t];
                b[1] = Ks[(nf * 8 + g) * KS_STR + kb * 8 + t + 4];
                mma_tf32(accS[nf], a, b);
            }
        }

        float r0 = -1e30f, r1 = -1e30f;
#pragma unroll
        for (int nf = 0; nf < 8; nf++) {
            r0 = fmaxf(r0, fmaxf(accS[nf][0], accS[nf][1]));
            r1 = fmaxf(r1, fmaxf(accS[nf][2], accS[nf][3]));
        }
        r0 = fmaxf(r0, __shfl_xor_sync(0xffffffffu, r0, 1));
        r0 = fmaxf(r0, __shfl_xor_sync(0xffffffffu, r0, 2));
        r1 = fmaxf(r1, __shfl_xor_sync(0xffffffffu, r1, 1));
        r1 = fmaxf(r1, __shfl_xor_sync(0xffffffffu, r1, 2));

        float mn0 = fmaxf(m0, r0);
        float mn1 = fmaxf(m1, r1);
        float al0 = __expf(m0 - mn0);
        float al1 = __expf(m1 - mn1);
        m0 = mn0; m1 = mn1;

        float s0 = 0.0f, s1 = 0.0f;
#pragma unroll
        for (int nf = 0; nf < 8; nf++) {
            float p00 = __expf(accS[nf][0] - m0);
            float p01 = __expf(accS[nf][1] - m0);
            float p10 = __expf(accS[nf][2] - m1);
            float p11 = __expf(accS[nf][3] - m1);
            s0 += p00 + p01;
            s1 += p10 + p11;
            int c = nf * 8 + 2 * t;
            Ps[(mr + g) * PS_STR + c]         = f2tf32(p00);
            Ps[(mr + g) * PS_STR + c + 1]     = f2tf32(p01);
            Ps[(mr + g + 8) * PS_STR + c]     = f2tf32(p10);
            Ps[(mr + g + 8) * PS_STR + c + 1] = f2tf32(p11);
        }
        s0 += __shfl_xor_sync(0xffffffffu, s0, 1);
        s0 += __shfl_xor_sync(0xffffffffu, s0, 2);
        s1 += __shfl_xor_sync(0xffffffffu, s1, 1);
        s1 += __shfl_xor_sync(0xffffffffu, s1, 2);
        l0 = l0 * al0 + s0;
        l1 = l1 * al1 + s1;

#pragma unroll
        for (int nf = 0; nf < 8; nf++) {
            accO[nf][0] *= al0;
            accO[nf][1] *= al0;
            accO[nf][2] *= al1;
            accO[nf][3] *= al1;
        }
        __syncwarp();

#pragma unroll
        for (int kb = 0; kb < 8; kb++) {
            uint32_t a[4];
            a[0] = Ps[(mr + g) * PS_STR + kb * 8 + t];
            a[1] = Ps[(mr + g + 8) * PS_STR + kb * 8 + t];
            a[2] = Ps[(mr + g) * PS_STR + kb * 8 + t + 4];
            a[3] = Ps[(mr + g + 8) * PS_STR + kb * 8 + t + 4];
#pragma unroll
            for (int nf = 0; nf < 8; nf++) {
                uint32_t b[2];
                b[0] = Vs[(kb * 8 + t) * VS_STR + nf * 8 + g];
                b[1] = Vs[(kb * 8 + t + 4) * VS_STR + nf * 8 + g];
                mma_tf32(accO[nf], a, b);
            }
        }
    }

    const float inv0 = 1.0f / l0;
    const float inv1 = 1.0f / l1;
    const int bb = bh >> 4, h = bh & 15;
    const int s0r = q0 + mr + g;
#pragma unroll
    for (int nf = 0; nf < 8; nf++) {
        int d = nf * 8 + 2 * t;
        float2 v0 = { __uint_as_float(f2tf32(accO[nf][0] * inv0)),
                      __uint_as_float(f2tf32(accO[nf][1] * inv0)) };
        float2 v1 = { __uint_as_float(f2tf32(accO[nf][2] * inv1)),
                      __uint_as_float(f2tf32(accO[nf][3] * inv1)) };
        *(float2*)(g_ctx + ((size_t)(bb * SS + s0r)) * HID + h * DD + d) = v0;
        *(float2*)(g_ctx + ((size_t)(bb * SS + s0r + 8)) * HID + h * DD + d) = v1;
    }
}

// ----------------------------------------------------------------------------
extern "C" void kernel_launch(void* const* d_in, const int* in_sizes, int n_in,
                              void* d_out, int out_size)
{
    const float* X  = (const float*)d_in[0];
    const float* Wq = (const float*)d_in[1];
    const float* bq = (const float*)d_in[2];
    const float* Wk = (const float*)d_in[3];
    const float* bk = (const float*)d_in[4];
    const float* Wv = (const float*)d_in[5];
    const float* bv = (const float*)d_in[6];
    const float* Wo = (const float*)d_in[7];
    const float* bo = (const float*)d_in[8];
    float* out = (float*)d_out;

    // Idempotent, not stream ops — graph-capture safe, no static guards.
    cudaFuncSetAttribute(flash_kernel,
                         cudaFuncAttributeMaxDynamicSharedMemorySize,
                         FLASH_SMEM_BYTES);
    cudaFuncSetAttribute(qkv_mma_kernel,
                         cudaFuncAttributeMaxDynamicSharedMemorySize,
                         GEMM_SMEM_BYTES);
    cudaFuncSetAttribute(oproj_mma_kernel,
                         cudaFuncAttributeMaxDynamicSharedMemorySize,
                         GEMM_SMEM_BYTES);

    // Pre-round X and weights to tf32 once (8M floats = 2M float4).
    round_kernel<<<8192, 256>>>(X, Wq, Wk, Wv, Wo);

    qkv_mma_kernel<<<dim3(HID / 128, MM / 128, 3), 256, GEMM_SMEM_BYTES>>>(bq, bk, bv);

    flash_kernel<<<dim3(SS / 128, BH), 256, FLASH_SMEM_BYTES>>>();

    oproj_mma_kernel<<<dim3(HID / 128, MM / 128), 256, GEMM_SMEM_BYTES>>>(bo, out);
}